// round 9
// baseline (speedup 1.0000x reference)
#include <cuda_runtime.h>
#include <cuda_fp16.h>
#include <cstdint>
#include <cstddef>

#define B_    64
#define T_    512
#define Dd    1024
#define Hh    1024
#define G3    3072
#define MROWS 32768          // B_*T_
#define NCTA  128            // persistent CTAs (<=148 SMs -> co-resident)
#define KC    128            // recurrence k-chunk

// ---------------- device scratch (no allocation) ----------------
__device__ float  g_xg[(size_t)MROWS * G3];      // input gates for current layer (fp32)
__device__ __half g_xf16[(size_t)MROWS * Dd];    // x as fp16
__device__ __half g_y0f16[(size_t)MROWS * Hh];   // layer-0 outputs fp16 (layer-1 GEMM input)
__device__ __half g_whi[(size_t)G3 * Dd];        // W_ih fp16 plane
__device__ __half g_hf16[2][B_ * Hh];            // h state fp16, double buffered
__device__ float  g_h0last[B_ * Hh];             // layer-0 final hidden (fp32)
__device__ unsigned g_flags[NCTA * 32];          // one flag per 128B line

// ---------------- helpers ----------------
__device__ __forceinline__ void mma_f16(float* c, const uint32_t* a, uint32_t b0, uint32_t b1) {
    asm volatile(
        "mma.sync.aligned.m16n8k16.row.col.f32.f16.f16.f32 "
        "{%0,%1,%2,%3}, {%4,%5,%6,%7}, {%8,%9}, {%0,%1,%2,%3};"
        : "+f"(c[0]), "+f"(c[1]), "+f"(c[2]), "+f"(c[3])
        : "r"(a[0]), "r"(a[1]), "r"(a[2]), "r"(a[3]), "r"(b0), "r"(b1));
}
__device__ __forceinline__ void ldsm_x4(uint32_t* r, const __half* p) {
    unsigned a = (unsigned)__cvta_generic_to_shared(p);
    asm volatile("ldmatrix.sync.aligned.m8n8.x4.shared.b16 {%0,%1,%2,%3}, [%4];"
                 : "=r"(r[0]), "=r"(r[1]), "=r"(r[2]), "=r"(r[3]) : "r"(a));
}
__device__ __forceinline__ void ldsm_x2(uint32_t* r, const __half* p) {
    unsigned a = (unsigned)__cvta_generic_to_shared(p);
    asm volatile("ldmatrix.sync.aligned.m8n8.x2.shared.b16 {%0,%1}, [%2];"
                 : "=r"(r[0]), "=r"(r[1]) : "r"(a));
}
__device__ __forceinline__ void cpa16(void* s, const void* g) {
    unsigned sa = (unsigned)__cvta_generic_to_shared(s);
    asm volatile("cp.async.cg.shared.global [%0], [%1], 16;" :: "r"(sa), "l"(g));
}
#define CP_COMMIT() asm volatile("cp.async.commit_group;")

// ---------------- conversion pre-pass kernels ----------------
__global__ void convx_kernel(const float* __restrict__ x) {
    size_t i = ((size_t)blockIdx.x * blockDim.x + threadIdx.x) * 4;
    if (i < (size_t)MROWS * Dd) {
        float4 v = *(const float4*)(x + i);
        *(__half2*)&g_xf16[i]     = __floats2half2_rn(v.x, v.y);
        *(__half2*)&g_xf16[i + 2] = __floats2half2_rn(v.z, v.w);
    }
}

__global__ void convw_kernel(const float* __restrict__ w) {
    size_t i = ((size_t)blockIdx.x * blockDim.x + threadIdx.x) * 4;
    if (i < (size_t)G3 * Dd) {
        float4 v = *(const float4*)(w + i);
        *(__half2*)&g_whi[i]     = __floats2half2_rn(v.x, v.y);
        *(__half2*)&g_whi[i + 2] = __floats2half2_rn(v.z, v.w);
    }
}

__global__ void split_h_kernel(const float* __restrict__ h0) {
    int i = blockIdx.x * blockDim.x + threadIdx.x;
    if (i < B_ * Hh) g_hf16[0][i] = __float2half_rn(h0[i]);
}

// ============ phase GEMM: g_xg[M,3072] = A_f16[M,1024] * Whi[3072,1024]^T + bias ============
#define GBM 128
#define GBN 128
#define GBK 64
#define GSTR 72              // 64 halves + 8 pad
#define GA_ST (GBM * GSTR)   // 9216
#define GB_ST (GBN * GSTR)   // 9216
#define NKT   (Dd / GBK)     // 16
#define GEMM_SMEM ((3 * (GA_ST + GB_ST)) * 2)   // 110592 bytes

__global__ void __launch_bounds__(256, 2) gemm_xg_kernel(int useY0,
                                                         const float* __restrict__ bias) {
    const __half* A = useY0 ? g_y0f16 : g_xf16;
    extern __shared__ __align__(16) __half gsm[];
    __half* sA = gsm;                    // [3][GA_ST]
    __half* sB = sA + 3 * GA_ST;         // [3][GB_ST]

    const int tid = threadIdx.x, lane = tid & 31, warp = tid >> 5;
    const int m0 = blockIdx.y * GBM, n0 = blockIdx.x * GBN;
    const int wm = (warp & 1) * 64, wn = (warp >> 1) * 32;
    const int g = lane >> 2, q2 = (lane & 3) * 2;

    const int aRow = lane & 15,                       aCol = (lane >> 4) << 3;
    const int bRow = ((lane >> 4) << 3) + (lane & 7), bCol = ((lane >> 3) & 1) << 3;

    float acc[4][4][4];
#pragma unroll
    for (int a = 0; a < 4; a++)
#pragma unroll
        for (int b = 0; b < 4; b++)
#pragma unroll
            for (int c = 0; c < 4; c++) acc[a][b][c] = 0.f;

    auto fill = [&](int st, int kt) {
        const int k0 = kt * GBK;
#pragma unroll
        for (int i = 0; i < 4; i++) {
            int f = tid + i * 256, row = f >> 3, s = f & 7;
            cpa16(sA + st * GA_ST + row * GSTR + s * 8,
                  A + (size_t)(m0 + row) * Dd + k0 + s * 8);
        }
#pragma unroll
        for (int i = 0; i < 4; i++) {
            int f = tid + i * 256, row = f >> 3, s = f & 7;
            cpa16(sB + st * GB_ST + row * GSTR + s * 8,
                  g_whi + (size_t)(n0 + row) * Dd + k0 + s * 8);
        }
        CP_COMMIT();
    };

    fill(0, 0);
    fill(1, 1);

    for (int kt = 0; kt < NKT; ++kt) {
        if (kt + 2 < NKT) asm volatile("cp.async.wait_group 1;");
        else              asm volatile("cp.async.wait_group 0;");
        __syncthreads();
        if (kt + 2 < NKT) fill((kt + 2) % 3, kt + 2);
        const int st = kt % 3;
        const __half* pA = sA + st * GA_ST;
        const __half* pB = sB + st * GB_ST;
#pragma unroll
        for (int kk = 0; kk < GBK; kk += 16) {
            uint32_t af[4][4];
#pragma unroll
            for (int mt = 0; mt < 4; mt++)
                ldsm_x4(af[mt], pA + (wm + mt * 16 + aRow) * GSTR + kk + aCol);
#pragma unroll
            for (int p = 0; p < 2; p++) {
                uint32_t bf[4];
                ldsm_x4(bf, pB + (wn + p * 16 + bRow) * GSTR + kk + bCol);
#pragma unroll
                for (int mt = 0; mt < 4; mt++) {
                    mma_f16(acc[mt][2 * p],     af[mt], bf[0], bf[1]);
                    mma_f16(acc[mt][2 * p + 1], af[mt], bf[2], bf[3]);
                }
            }
        }
        __syncthreads();
    }
#pragma unroll
    for (int mt = 0; mt < 4; mt++) {
        int row = m0 + wm + mt * 16 + g;
#pragma unroll
        for (int nt = 0; nt < 4; nt++) {
            int col = n0 + wn + nt * 8 + q2;
            float b0 = __ldg(bias + col), b1 = __ldg(bias + col + 1);
            *(float2*)(g_xg + (size_t)row * G3 + col) =
                make_float2(acc[mt][nt][0] + b0, acc[mt][nt][1] + b1);
            *(float2*)(g_xg + (size_t)(row + 8) * G3 + col) =
                make_float2(acc[mt][nt][2] + b0, acc[mt][nt][3] + b1);
        }
    }
}

// ======== persistent recurrence: 2D partition, all W in registers, split gate tail ========
#define WSTR2 1032
#define RSMEM2 ((96 * WSTR2 + 8 * 16 * 128) * 2)   // 230,912 bytes

__global__ void __launch_bounds__(256, 1) recur_kernel(const float* __restrict__ h0,
                                                       const float* __restrict__ w_hh,
                                                       const float* __restrict__ b_hh,
                                                       float* __restrict__ yout) {
    const int layer0 = (yout == nullptr);
    extern __shared__ __align__(16) __half smem[];
    __half* sW = smem;                       // [96][WSTR2] (dead after init -> scratch)
    __half* sH = sW + 96 * WSTR2;            // [8][16][128] swizzled

    const int tid = threadIdx.x, lane = tid & 31, warp = tid >> 5;
    const int w4 = warp & 3, wg = warp >> 2;
    const int cg = blockIdx.x & 31, bg = blockIdx.x >> 5;
    const int gid = blockIdx.x;
    const int g = lane >> 2, q2 = (lane & 3) * 2;

    const unsigned base = g_flags[gid * 32];   // monotonic (replay-safe)

    // ---- load W_hh into smem (staging): rows = w4*24 + gate*8 + c8, cols = k
    for (int f = tid; f < 96 * 128; f += 256) {
        int rowp = f >> 7, seg = f & 127;
        int w4r = rowp / 24, rem = rowp - w4r * 24;
        int gate = rem >> 3, c8 = rem & 7;
        const float* src = w_hh + (size_t)(gate * Hh + cg * 32 + w4r * 8 + c8) * Hh + seg * 8;
        float4 v0 = *(const float4*)src;
        float4 v1 = *(const float4*)(src + 4);
        __half* d = sW + rowp * WSTR2 + seg * 8;
        ((__half2*)d)[0] = __floats2half2_rn(v0.x, v0.y);
        ((__half2*)d)[1] = __floats2half2_rn(v0.z, v0.w);
        ((__half2*)d)[2] = __floats2half2_rn(v1.x, v1.y);
        ((__half2*)d)[3] = __floats2half2_rn(v1.z, v1.w);
    }
    __syncthreads();

    // fragment selectors
    const int aRow = lane & 15, aSeg = lane >> 4;
    const int bRow = ((lane >> 4) << 3) + (lane & 7), bCol = ((lane >> 3) & 1) << 3;
    const int nRow = lane & 7;
    const int myChunk = wg * 4 + w4;
    const int kbase = wg * 512;
    const int wb = w4 * 24;

    // ---- ALL W fragments -> registers (once, reused all 512 steps)
    uint32_t wreg[32][4];   // r,z gates
    uint32_t wn[32][2];     // n gate
#pragma unroll
    for (int kk = 0; kk < 32; kk++) {
        ldsm_x4(wreg[kk], sW + (wb + bRow) * WSTR2 + kbase + kk * 16 + bCol);
        ldsm_x2(wn[kk],   sW + (wb + 16 + nRow) * WSTR2 + kbase + kk * 16 + bCol);
    }
    __syncthreads();   // sW now dead -> reusable as scratch

    // per-thread output coords: wg0 owns row rb0, wg1 owns row rb1
    const int ncol = cg * 32 + w4 * 8 + q2;
    const int rb0 = bg * 16 + g;
    const int myRow = wg ? rb0 + 8 : rb0;

    float bh[3][2];
#pragma unroll
    for (int gg = 0; gg < 3; gg++) {
        bh[gg][0] = b_hh[gg * Hh + ncol];
        bh[gg][1] = b_hh[gg * Hh + ncol + 1];
    }
    float hprev[2];
    hprev[0] = h0[myRow * Hh + ncol];
    hprev[1] = h0[myRow * Hh + ncol + 1];

    const float* xgp = g_xg + (size_t)myRow * T_ * G3 + ncol;
    float* scratch = (float*)sW;

    for (int t = 0; t < T_; ++t) {
        const int pb = t & 1, nb = pb ^ 1;

        if (t) {  // barrier among the 32 CTAs sharing this bg
            __threadfence();
            __syncthreads();
            if (tid == 0)
                asm volatile("st.release.gpu.u32 [%0], %1;"
                             :: "l"(&g_flags[gid * 32]), "r"(base + (unsigned)t));
            if (tid < 32) {
                unsigned v;
                do { asm volatile("ld.acquire.gpu.u32 %0, [%1];"
                                  : "=r"(v) : "l"(&g_flags[(bg * 32 + tid) * 32])); }
                while (v < base + (unsigned)t);
            }
            __syncthreads();
        }

        // each warp streams its chunk (16 rows x 128 halves, swizzled), one commit group
#pragma unroll
        for (int i = 0; i < 8; i++) {
            int f = lane + i * 32;
            int r = f >> 4, sj = f & 15;
            int sjs = sj ^ (r & 7);
            cpa16(sH + myChunk * 2048 + r * 128 + sjs * 8,
                  &g_hf16[pb][(size_t)(bg * 16 + r) * Hh + myChunk * KC + sj * 8]);
        }
        CP_COMMIT();

        // prefetch gate inputs for my row (overlaps with cp.async)
        float2 a0 = *(const float2*)(xgp);
        float2 a1 = *(const float2*)(xgp + Hh);
        float2 a2 = *(const float2*)(xgp + 2 * Hh);
        xgp += G3;

        asm volatile("cp.async.wait_group 0;");
        __syncthreads();

        float acc[3][4];
#pragma unroll
        for (int gg = 0; gg < 3; gg++)
#pragma unroll
            for (int i = 0; i < 4; i++) acc[gg][i] = 0.f;

#pragma unroll
        for (int kk = 0; kk < 32; kk++) {
            const int slot = wg * 4 + (kk >> 3);
            const __half* hBase = sH + slot * 2048 + aRow * 128;
            const int seg = (((kk & 7) * 2 + aSeg) ^ (aRow & 7));
            uint32_t af[4];
            ldsm_x4(af, hBase + seg * 8);
            mma_f16(acc[0], af, wreg[kk][0], wreg[kk][1]);
            mma_f16(acc[1], af, wreg[kk][2], wreg[kk][3]);
            mma_f16(acc[2], af, wn[kk][0], wn[kk][1]);
        }

        // exchange partner halves via scratch (sW region; no conflict with sH)
        const int iw = wg ? 0 : 2;    // write the half the partner needs
#pragma unroll
        for (int gg = 0; gg < 3; gg++) {
            scratch[tid * 6 + gg * 2]     = acc[gg][iw];
            scratch[tid * 6 + gg * 2 + 1] = acc[gg][iw + 1];
        }
        __syncthreads();
        const int partner = tid ^ 128;
        const int im = wg ? 2 : 0;    // the half I finish
        float s0[3], s1[3];
#pragma unroll
        for (int gg = 0; gg < 3; gg++) {
            s0[gg] = acc[gg][im]     + scratch[partner * 6 + gg * 2];
            s1[gg] = acc[gg][im + 1] + scratch[partner * 6 + gg * 2 + 1];
        }

        // gate math: 2 outputs per thread (row myRow, cols ncol, ncol+1)
        float hnew[2];
        {
            float r0 = 1.f / (1.f + __expf(-(a0.x + s0[0] + bh[0][0])));
            float z0 = 1.f / (1.f + __expf(-(a1.x + s0[1] + bh[1][0])));
            float n0 = tanhf(a2.x + r0 * (s0[2] + bh[2][0]));
            hnew[0] = (1.f - z0) * n0 + z0 * hprev[0];
            float r1 = 1.f / (1.f + __expf(-(a0.y + s1[0] + bh[0][1])));
            float z1 = 1.f / (1.f + __expf(-(a1.y + s1[1] + bh[1][1])));
            float n1 = tanhf(a2.y + r1 * (s1[2] + bh[2][1]));
            hnew[1] = (1.f - z1) * n1 + z1 * hprev[1];
            hprev[0] = hnew[0];
            hprev[1] = hnew[1];
        }

        if (layer0) {
            *(__half2*)&g_y0f16[((size_t)(myRow * T_ + t)) * Hh + ncol] =
                __floats2half2_rn(hnew[0], hnew[1]);
            if (t == T_ - 1)
                *(float2*)&g_h0last[myRow * Hh + ncol] = make_float2(hnew[0], hnew[1]);
        } else {
            *(float2*)(yout + ((size_t)(myRow * T_ + t)) * Hh + ncol) =
                make_float2(hnew[0], hnew[1]);
        }
        *(__half2*)&g_hf16[nb][myRow * Hh + ncol] = __floats2half2_rn(hnew[0], hnew[1]);
    }
}

// ---------------- tail: final hidden states ----------------
__global__ void tail_kernel(const float* __restrict__ y1, float* __restrict__ outh) {
    int i = blockIdx.x * blockDim.x + threadIdx.x;   // 0 .. 2*B*H-1
    if (i >= 2 * B_ * Hh) return;
    if (i < B_ * Hh) {
        outh[i] = g_h0last[i];
    } else {
        int j = i - B_ * Hh;
        int b = j >> 10, c = j & 1023;
        outh[i] = y1[((size_t)(b * T_ + (T_ - 1))) * Hh + c];
    }
}

// ---------------- launch ----------------
extern "C" void kernel_launch(void* const* d_in, const int* in_sizes, int n_in,
                              void* d_out, int out_size) {
    const float* x      = (const float*)d_in[0];
    const float* hidden = (const float*)d_in[1];
    const float* w_ih0  = (const float*)d_in[2];
    const float* w_hh0  = (const float*)d_in[3];
    const float* b_ih0  = (const float*)d_in[4];
    const float* b_hh0  = (const float*)d_in[5];
    const float* w_ih1  = (const float*)d_in[6];
    const float* w_hh1  = (const float*)d_in[7];
    const float* b_ih1  = (const float*)d_in[8];
    const float* b_hh1  = (const float*)d_in[9];
    float* out = (float*)d_out;

    cudaFuncSetAttribute(recur_kernel, cudaFuncAttributeMaxDynamicSharedMemorySize, RSMEM2);
    cudaFuncSetAttribute(gemm_xg_kernel, cudaFuncAttributeMaxDynamicSharedMemorySize, GEMM_SMEM);

    dim3 ggrid(G3 / GBN, MROWS / GBM);

    // layer 0
    convx_kernel<<<(MROWS * Dd / 4 + 255) / 256, 256>>>(x);
    convw_kernel<<<(G3 * Dd / 4 + 255) / 256, 256>>>(w_ih0);
    split_h_kernel<<<(B_ * Hh + 255) / 256, 256>>>(hidden);
    gemm_xg_kernel<<<ggrid, 256, GEMM_SMEM>>>(0, b_ih0);
    recur_kernel<<<NCTA, 256, RSMEM2>>>(hidden, w_hh0, b_hh0, nullptr);

    // layer 1
    convw_kernel<<<(G3 * Dd / 4 + 255) / 256, 256>>>(w_ih1);
    split_h_kernel<<<(B_ * Hh + 255) / 256, 256>>>(hidden + B_ * Hh);
    gemm_xg_kernel<<<ggrid, 256, GEMM_SMEM>>>(1, b_ih1);
    recur_kernel<<<NCTA, 256, RSMEM2>>>(hidden + B_ * Hh, w_hh1, b_hh1, out);

    // final hidden states (only if the output buffer includes them)
    if (out_size >= MROWS * Hh + 2 * B_ * Hh) {
        tail_kernel<<<(2 * B_ * Hh + 255) / 256, 256>>>(out, out + (size_t)MROWS * Hh);
    }
}

// round 10
// speedup vs baseline: 1.0070x; 1.0070x over previous
#include <cuda_runtime.h>
#include <cuda_fp16.h>
#include <cstdint>
#include <cstddef>

#define B_    64
#define T_    512
#define Dd    1024
#define Hh    1024
#define G3    3072
#define MROWS 32768          // B_*T_
#define NCTA  128            // persistent CTAs (<=148 SMs -> co-resident)
#define KC    128            // recurrence k-chunk

// ---------------- device scratch (no allocation) ----------------
__device__ float  g_xg[(size_t)MROWS * G3];      // input gates for current layer (fp32)
__device__ __half g_xf16[(size_t)MROWS * Dd];    // x as fp16
__device__ __half g_y0f16[(size_t)MROWS * Hh];   // layer-0 outputs fp16 (layer-1 GEMM input)
__device__ __half g_whi[(size_t)G3 * Dd];        // W_ih fp16 plane
__device__ __half g_hf16[2][B_ * Hh];            // h state fp16, double buffered
__device__ float  g_h0last[B_ * Hh];             // layer-0 final hidden (fp32)
__device__ unsigned g_flags[NCTA * 32];          // one flag per 128B line

// ---------------- helpers ----------------
__device__ __forceinline__ void mma_f16(float* c, const uint32_t* a, uint32_t b0, uint32_t b1) {
    asm volatile(
        "mma.sync.aligned.m16n8k16.row.col.f32.f16.f16.f32 "
        "{%0,%1,%2,%3}, {%4,%5,%6,%7}, {%8,%9}, {%0,%1,%2,%3};"
        : "+f"(c[0]), "+f"(c[1]), "+f"(c[2]), "+f"(c[3])
        : "r"(a[0]), "r"(a[1]), "r"(a[2]), "r"(a[3]), "r"(b0), "r"(b1));
}
__device__ __forceinline__ void ldsm_x4(uint32_t* r, const __half* p) {
    unsigned a = (unsigned)__cvta_generic_to_shared(p);
    asm volatile("ldmatrix.sync.aligned.m8n8.x4.shared.b16 {%0,%1,%2,%3}, [%4];"
                 : "=r"(r[0]), "=r"(r[1]), "=r"(r[2]), "=r"(r[3]) : "r"(a));
}
__device__ __forceinline__ void ldsm_x2(uint32_t* r, const __half* p) {
    unsigned a = (unsigned)__cvta_generic_to_shared(p);
    asm volatile("ldmatrix.sync.aligned.m8n8.x2.shared.b16 {%0,%1}, [%2];"
                 : "=r"(r[0]), "=r"(r[1]) : "r"(a));
}
__device__ __forceinline__ void cpa16(void* s, const void* g) {
    unsigned sa = (unsigned)__cvta_generic_to_shared(s);
    asm volatile("cp.async.cg.shared.global [%0], [%1], 16;" :: "r"(sa), "l"(g));
}
#define CP_COMMIT() asm volatile("cp.async.commit_group;")

// ---------------- conversion pre-pass kernels ----------------
__global__ void convx_kernel(const float* __restrict__ x) {
    size_t i = ((size_t)blockIdx.x * blockDim.x + threadIdx.x) * 4;
    if (i < (size_t)MROWS * Dd) {
        float4 v = *(const float4*)(x + i);
        *(__half2*)&g_xf16[i]     = __floats2half2_rn(v.x, v.y);
        *(__half2*)&g_xf16[i + 2] = __floats2half2_rn(v.z, v.w);
    }
}

__global__ void convw_kernel(const float* __restrict__ w) {
    size_t i = ((size_t)blockIdx.x * blockDim.x + threadIdx.x) * 4;
    if (i < (size_t)G3 * Dd) {
        float4 v = *(const float4*)(w + i);
        *(__half2*)&g_whi[i]     = __floats2half2_rn(v.x, v.y);
        *(__half2*)&g_whi[i + 2] = __floats2half2_rn(v.z, v.w);
    }
}

__global__ void split_h_kernel(const float* __restrict__ h0) {
    int i = blockIdx.x * blockDim.x + threadIdx.x;
    if (i < B_ * Hh) g_hf16[0][i] = __float2half_rn(h0[i]);
}

// ============ phase GEMM: g_xg[M,3072] = A_f16[M,1024] * Whi[3072,1024]^T + bias ============
#define GBM 128
#define GBN 128
#define GBK 64
#define GSTR 72              // 64 halves + 8 pad
#define GA_ST (GBM * GSTR)   // 9216
#define GB_ST (GBN * GSTR)   // 9216
#define NKT   (Dd / GBK)     // 16
#define GEMM_SMEM ((3 * (GA_ST + GB_ST)) * 2)   // 110592 bytes

__global__ void __launch_bounds__(256, 2) gemm_xg_kernel(int useY0,
                                                         const float* __restrict__ bias) {
    const __half* A = useY0 ? g_y0f16 : g_xf16;
    extern __shared__ __align__(16) __half gsm[];
    __half* sA = gsm;                    // [3][GA_ST]
    __half* sB = sA + 3 * GA_ST;         // [3][GB_ST]

    const int tid = threadIdx.x, lane = tid & 31, warp = tid >> 5;
    const int m0 = blockIdx.y * GBM, n0 = blockIdx.x * GBN;
    const int wm = (warp & 1) * 64, wn = (warp >> 1) * 32;
    const int g = lane >> 2, q2 = (lane & 3) * 2;

    const int aRow = lane & 15,                       aCol = (lane >> 4) << 3;
    const int bRow = ((lane >> 4) << 3) + (lane & 7), bCol = ((lane >> 3) & 1) << 3;

    float acc[4][4][4];
#pragma unroll
    for (int a = 0; a < 4; a++)
#pragma unroll
        for (int b = 0; b < 4; b++)
#pragma unroll
            for (int c = 0; c < 4; c++) acc[a][b][c] = 0.f;

    auto fill = [&](int st, int kt) {
        const int k0 = kt * GBK;
#pragma unroll
        for (int i = 0; i < 4; i++) {
            int f = tid + i * 256, row = f >> 3, s = f & 7;
            cpa16(sA + st * GA_ST + row * GSTR + s * 8,
                  A + (size_t)(m0 + row) * Dd + k0 + s * 8);
        }
#pragma unroll
        for (int i = 0; i < 4; i++) {
            int f = tid + i * 256, row = f >> 3, s = f & 7;
            cpa16(sB + st * GB_ST + row * GSTR + s * 8,
                  g_whi + (size_t)(n0 + row) * Dd + k0 + s * 8);
        }
        CP_COMMIT();
    };

    fill(0, 0);
    fill(1, 1);

    for (int kt = 0; kt < NKT; ++kt) {
        if (kt + 2 < NKT) asm volatile("cp.async.wait_group 1;");
        else              asm volatile("cp.async.wait_group 0;");
        __syncthreads();
        if (kt + 2 < NKT) fill((kt + 2) % 3, kt + 2);
        const int st = kt % 3;
        const __half* pA = sA + st * GA_ST;
        const __half* pB = sB + st * GB_ST;
#pragma unroll
        for (int kk = 0; kk < GBK; kk += 16) {
            uint32_t af[4][4];
#pragma unroll
            for (int mt = 0; mt < 4; mt++)
                ldsm_x4(af[mt], pA + (wm + mt * 16 + aRow) * GSTR + kk + aCol);
#pragma unroll
            for (int p = 0; p < 2; p++) {
                uint32_t bf[4];
                ldsm_x4(bf, pB + (wn + p * 16 + bRow) * GSTR + kk + bCol);
#pragma unroll
                for (int mt = 0; mt < 4; mt++) {
                    mma_f16(acc[mt][2 * p],     af[mt], bf[0], bf[1]);
                    mma_f16(acc[mt][2 * p + 1], af[mt], bf[2], bf[3]);
                }
            }
        }
        __syncthreads();
    }
#pragma unroll
    for (int mt = 0; mt < 4; mt++) {
        int row = m0 + wm + mt * 16 + g;
#pragma unroll
        for (int nt = 0; nt < 4; nt++) {
            int col = n0 + wn + nt * 8 + q2;
            float b0 = __ldg(bias + col), b1 = __ldg(bias + col + 1);
            *(float2*)(g_xg + (size_t)row * G3 + col) =
                make_float2(acc[mt][nt][0] + b0, acc[mt][nt][1] + b1);
            *(float2*)(g_xg + (size_t)(row + 8) * G3 + col) =
                make_float2(acc[mt][nt][2] + b0, acc[mt][nt][3] + b1);
        }
    }
}

// ======== persistent recurrence: 2D partition, r/z W in registers, n W in smem ========
// (R8-winning compute loop + split gate tail)
#define WSTR2 1032
#define RSMEM2 ((96 * WSTR2 + 8 * 16 * 128) * 2)   // 230,912 bytes

__global__ void __launch_bounds__(256, 1) recur_kernel(const float* __restrict__ h0,
                                                       const float* __restrict__ w_hh,
                                                       const float* __restrict__ b_hh,
                                                       float* __restrict__ yout) {
    const int layer0 = (yout == nullptr);
    extern __shared__ __align__(16) __half smem[];
    __half* sW = smem;                       // [96][WSTR2]
    __half* sH = sW + 96 * WSTR2;            // [8][16][128] swizzled

    const int tid = threadIdx.x, lane = tid & 31, warp = tid >> 5;
    const int w4 = warp & 3, wg = warp >> 2;
    const int cg = blockIdx.x & 31, bg = blockIdx.x >> 5;
    const int gid = blockIdx.x;
    const int g = lane >> 2, q2 = (lane & 3) * 2;

    const unsigned base = g_flags[gid * 32];   // monotonic (replay-safe)

    // ---- load W_hh into smem: rows = w4*24 + gate*8 + c8, cols = k
    for (int f = tid; f < 96 * 128; f += 256) {
        int rowp = f >> 7, seg = f & 127;
        int w4r = rowp / 24, rem = rowp - w4r * 24;
        int gate = rem >> 3, c8 = rem & 7;
        const float* src = w_hh + (size_t)(gate * Hh + cg * 32 + w4r * 8 + c8) * Hh + seg * 8;
        float4 v0 = *(const float4*)src;
        float4 v1 = *(const float4*)(src + 4);
        __half* d = sW + rowp * WSTR2 + seg * 8;
        ((__half2*)d)[0] = __floats2half2_rn(v0.x, v0.y);
        ((__half2*)d)[1] = __floats2half2_rn(v0.z, v0.w);
        ((__half2*)d)[2] = __floats2half2_rn(v1.x, v1.y);
        ((__half2*)d)[3] = __floats2half2_rn(v1.z, v1.w);
    }
    __syncthreads();

    // fragment selectors
    const int aRow = lane & 15, aSeg = lane >> 4;
    const int bRow = ((lane >> 4) << 3) + (lane & 7), bCol = ((lane >> 3) & 1) << 3;
    const int nRow = lane & 7;
    const int myChunk = wg * 4 + w4;
    const int kbase = wg * 512;
    const int wb = w4 * 24;

    // ---- r,z-gate W fragments -> registers (once, reused all 512 steps)
    uint32_t wreg[32][4];
#pragma unroll
    for (int kk = 0; kk < 32; kk++)
        ldsm_x4(wreg[kk], sW + (wb + bRow) * WSTR2 + kbase + kk * 16 + bCol);

    // per-thread output coords: wg0 owns row rb0, wg1 owns row rb0+8
    const int ncol = cg * 32 + w4 * 8 + q2;
    const int rb0 = bg * 16 + g;
    const int myRow = wg ? rb0 + 8 : rb0;

    float bh[3][2];
#pragma unroll
    for (int gg = 0; gg < 3; gg++) {
        bh[gg][0] = b_hh[gg * Hh + ncol];
        bh[gg][1] = b_hh[gg * Hh + ncol + 1];
    }
    float hprev[2];
    hprev[0] = h0[myRow * Hh + ncol];
    hprev[1] = h0[myRow * Hh + ncol + 1];

    const float* xgp = g_xg + (size_t)myRow * T_ * G3 + ncol;
    // scratch lives in the sH slot-0/1 region (6 KB); those slots are fully
    // consumed before any warp reaches the tail (round-2 sync precedes round 3).
    float* scratch = (float*)sH;

    for (int t = 0; t < T_; ++t) {
        const int pb = t & 1, nb = pb ^ 1;

        // prefetch gate inputs for my row (overlaps the barrier + stream)
        float2 a0 = *(const float2*)(xgp);
        float2 a1 = *(const float2*)(xgp + Hh);
        float2 a2 = *(const float2*)(xgp + 2 * Hh);
        xgp += G3;

        if (t) {  // barrier among the 32 CTAs sharing this bg
            __threadfence();
            __syncthreads();
            if (tid == 0)
                asm volatile("st.release.gpu.u32 [%0], %1;"
                             :: "l"(&g_flags[gid * 32]), "r"(base + (unsigned)t));
            if (tid < 32) {
                unsigned v;
                do { asm volatile("ld.acquire.gpu.u32 %0, [%1];"
                                  : "=r"(v) : "l"(&g_flags[(bg * 32 + tid) * 32])); }
                while (v < base + (unsigned)t);
            }
            __syncthreads();
        }

        // each warp streams its chunk (16 rows x 128 halves, swizzled), one commit group
#pragma unroll
        for (int i = 0; i < 8; i++) {
            int f = lane + i * 32;
            int r = f >> 4, sj = f & 15;
            int sjs = sj ^ (r & 7);
            cpa16(sH + myChunk * 2048 + r * 128 + sjs * 8,
                  &g_hf16[pb][(size_t)(bg * 16 + r) * Hh + myChunk * KC + sj * 8]);
        }
        CP_COMMIT();

        float acc[3][4];
#pragma unroll
        for (int gg = 0; gg < 3; gg++)
#pragma unroll
            for (int i = 0; i < 4; i++) acc[gg][i] = 0.f;

#pragma unroll
        for (int j = 0; j < 4; ++j) {
            if (w4 == j) asm volatile("cp.async.wait_group 0;");
            __syncthreads();
            const int slot = wg * 4 + j;
            const __half* hBase = sH + slot * 2048 + aRow * 128;
            const int sw = (aRow & 7);
#pragma unroll
            for (int kk = 0; kk < 8; kk++) {
                uint32_t af[4];
                int seg = kk * 2 + aSeg;
                ldsm_x4(af, hBase + (seg ^ sw) * 8);
                const int gcol = kbase + j * KC + kk * 16;
                uint32_t w2[2];
                ldsm_x2(w2, sW + (wb + 16 + nRow) * WSTR2 + gcol + bCol);
                const uint32_t* w01 = wreg[j * 8 + kk];
                mma_f16(acc[0], af, w01[0], w01[1]);
                mma_f16(acc[1], af, w01[2], w01[3]);
                mma_f16(acc[2], af, w2[0], w2[1]);
            }
        }

        // split tail: exchange partner halves via scratch, each wg finishes its row
        const int iw = wg ? 0 : 2;    // write the half the partner needs
#pragma unroll
        for (int gg = 0; gg < 3; gg++) {
            scratch[tid * 6 + gg * 2]     = acc[gg][iw];
            scratch[tid * 6 + gg * 2 + 1] = acc[gg][iw + 1];
        }
        __syncthreads();
        const int partner = tid ^ 128;
        const int im = wg ? 2 : 0;    // the half I finish
        float s0[3], s1[3];
#pragma unroll
        for (int gg = 0; gg < 3; gg++) {
            s0[gg] = acc[gg][im]     + scratch[partner * 6 + gg * 2];
            s1[gg] = acc[gg][im + 1] + scratch[partner * 6 + gg * 2 + 1];
        }

        // gate math: 2 outputs per thread (row myRow, cols ncol, ncol+1)
        float hnew[2];
        {
            float r0 = 1.f / (1.f + __expf(-(a0.x + s0[0] + bh[0][0])));
            float z0 = 1.f / (1.f + __expf(-(a1.x + s0[1] + bh[1][0])));
            float n0 = tanhf(a2.x + r0 * (s0[2] + bh[2][0]));
            hnew[0] = (1.f - z0) * n0 + z0 * hprev[0];
            float r1 = 1.f / (1.f + __expf(-(a0.y + s1[0] + bh[0][1])));
            float z1 = 1.f / (1.f + __expf(-(a1.y + s1[1] + bh[1][1])));
            float n1 = tanhf(a2.y + r1 * (s1[2] + bh[2][1]));
            hnew[1] = (1.f - z1) * n1 + z1 * hprev[1];
            hprev[0] = hnew[0];
            hprev[1] = hnew[1];
        }

        if (layer0) {
            *(__half2*)&g_y0f16[((size_t)(myRow * T_ + t)) * Hh + ncol] =
                __floats2half2_rn(hnew[0], hnew[1]);
            if (t == T_ - 1)
                *(float2*)&g_h0last[myRow * Hh + ncol] = make_float2(hnew[0], hnew[1]);
        } else {
            *(float2*)(yout + ((size_t)(myRow * T_ + t)) * Hh + ncol) =
                make_float2(hnew[0], hnew[1]);
        }
        *(__half2*)&g_hf16[nb][myRow * Hh + ncol] = __floats2half2_rn(hnew[0], hnew[1]);
    }
}

// ---------------- tail: final hidden states ----------------
__global__ void tail_kernel(const float* __restrict__ y1, float* __restrict__ outh) {
    int i = blockIdx.x * blockDim.x + threadIdx.x;   // 0 .. 2*B*H-1
    if (i >= 2 * B_ * Hh) return;
    if (i < B_ * Hh) {
        outh[i] = g_h0last[i];
    } else {
        int j = i - B_ * Hh;
        int b = j >> 10, c = j & 1023;
        outh[i] = y1[((size_t)(b * T_ + (T_ - 1))) * Hh + c];
    }
}

// ---------------- launch ----------------
extern "C" void kernel_launch(void* const* d_in, const int* in_sizes, int n_in,
                              void* d_out, int out_size) {
    const float* x      = (const float*)d_in[0];
    const float* hidden = (const float*)d_in[1];
    const float* w_ih0  = (const float*)d_in[2];
    const float* w_hh0  = (const float*)d_in[3];
    const float* b_ih0  = (const float*)d_in[4];
    const float* b_hh0  = (const float*)d_in[5];
    const float* w_ih1  = (const float*)d_in[6];
    const float* w_hh1  = (const float*)d_in[7];
    const float* b_ih1  = (const float*)d_in[8];
    const float* b_hh1  = (const float*)d_in[9];
    float* out = (float*)d_out;

    cudaFuncSetAttribute(recur_kernel, cudaFuncAttributeMaxDynamicSharedMemorySize, RSMEM2);
    cudaFuncSetAttribute(gemm_xg_kernel, cudaFuncAttributeMaxDynamicSharedMemorySize, GEMM_SMEM);

    dim3 ggrid(G3 / GBN, MROWS / GBM);

    // layer 0
    convx_kernel<<<(MROWS * Dd / 4 + 255) / 256, 256>>>(x);
    convw_kernel<<<(G3 * Dd / 4 + 255) / 256, 256>>>(w_ih0);
    split_h_kernel<<<(B_ * Hh + 255) / 256, 256>>>(hidden);
    gemm_xg_kernel<<<ggrid, 256, GEMM_SMEM>>>(0, b_ih0);
    recur_kernel<<<NCTA, 256, RSMEM2>>>(hidden, w_hh0, b_hh0, nullptr);

    // layer 1
    convw_kernel<<<(G3 * Dd / 4 + 255) / 256, 256>>>(w_ih1);
    split_h_kernel<<<(B_ * Hh + 255) / 256, 256>>>(hidden + B_ * Hh);
    gemm_xg_kernel<<<ggrid, 256, GEMM_SMEM>>>(1, b_ih1);
    recur_kernel<<<NCTA, 256, RSMEM2>>>(hidden + B_ * Hh, w_hh1, b_hh1, out);

    // final hidden states (only if the output buffer includes them)
    if (out_size >= MROWS * Hh + 2 * B_ * Hh) {
        tail_kernel<<<(2 * B_ * Hh + 255) / 256, 256>>>(out, out + (size_t)MROWS * Hh);
    }
}

// round 11
// speedup vs baseline: 1.0112x; 1.0041x over previous
#include <cuda_runtime.h>
#include <cuda_fp16.h>
#include <cstdint>
#include <cstddef>

#define B_    64
#define T_    512
#define Dd    1024
#define Hh    1024
#define G3    3072
#define MROWS 32768          // B_*T_
#define NCTA  128            // persistent CTAs (<=148 SMs -> co-resident)
#define KC    128            // recurrence k-chunk

// ---------------- device scratch (no allocation) ----------------
__device__ float  g_xg[(size_t)MROWS * G3];      // input gates for current layer (fp32)
__device__ __half g_xf16[(size_t)MROWS * Dd];    // x as fp16
__device__ __half g_y0f16[(size_t)MROWS * Hh];   // layer-0 outputs fp16 (layer-1 GEMM input)
__device__ __half g_whi[(size_t)G3 * Dd];        // W_ih fp16 plane
__device__ __half g_hf16[2][B_ * Hh];            // h state fp16, double buffered
__device__ float  g_h0last[B_ * Hh];             // layer-0 final hidden (fp32)
__device__ unsigned g_flags[NCTA * 32];          // one flag per 128B line

// ---------------- helpers ----------------
__device__ __forceinline__ void mma_f16(float* c, const uint32_t* a, uint32_t b0, uint32_t b1) {
    asm volatile(
        "mma.sync.aligned.m16n8k16.row.col.f32.f16.f16.f32 "
        "{%0,%1,%2,%3}, {%4,%5,%6,%7}, {%8,%9}, {%0,%1,%2,%3};"
        : "+f"(c[0]), "+f"(c[1]), "+f"(c[2]), "+f"(c[3])
        : "r"(a[0]), "r"(a[1]), "r"(a[2]), "r"(a[3]), "r"(b0), "r"(b1));
}
__device__ __forceinline__ void ldsm_x4(uint32_t* r, const __half* p) {
    unsigned a = (unsigned)__cvta_generic_to_shared(p);
    asm volatile("ldmatrix.sync.aligned.m8n8.x4.shared.b16 {%0,%1,%2,%3}, [%4];"
                 : "=r"(r[0]), "=r"(r[1]), "=r"(r[2]), "=r"(r[3]) : "r"(a));
}
__device__ __forceinline__ void ldsm_x2(uint32_t* r, const __half* p) {
    unsigned a = (unsigned)__cvta_generic_to_shared(p);
    asm volatile("ldmatrix.sync.aligned.m8n8.x2.shared.b16 {%0,%1}, [%2];"
                 : "=r"(r[0]), "=r"(r[1]) : "r"(a));
}
__device__ __forceinline__ void cpa16(void* s, const void* g) {
    unsigned sa = (unsigned)__cvta_generic_to_shared(s);
    asm volatile("cp.async.cg.shared.global [%0], [%1], 16;" :: "r"(sa), "l"(g));
}
#define CP_COMMIT() asm volatile("cp.async.commit_group;")

// ---------------- conversion pre-pass kernels ----------------
__global__ void convx_kernel(const float* __restrict__ x) {
    size_t i = ((size_t)blockIdx.x * blockDim.x + threadIdx.x) * 4;
    if (i < (size_t)MROWS * Dd) {
        float4 v = *(const float4*)(x + i);
        *(__half2*)&g_xf16[i]     = __floats2half2_rn(v.x, v.y);
        *(__half2*)&g_xf16[i + 2] = __floats2half2_rn(v.z, v.w);
    }
}

__global__ void convw_kernel(const float* __restrict__ w) {
    size_t i = ((size_t)blockIdx.x * blockDim.x + threadIdx.x) * 4;
    if (i < (size_t)G3 * Dd) {
        float4 v = *(const float4*)(w + i);
        *(__half2*)&g_whi[i]     = __floats2half2_rn(v.x, v.y);
        *(__half2*)&g_whi[i + 2] = __floats2half2_rn(v.z, v.w);
    }
}

__global__ void split_h_kernel(const float* __restrict__ h0) {
    int i = blockIdx.x * blockDim.x + threadIdx.x;
    if (i < B_ * Hh) g_hf16[0][i] = __float2half_rn(h0[i]);
}

// ============ phase GEMM: g_xg[M,3072] = A_f16[M,1024] * Whi[3072,1024]^T + bias ============
#define GBM 128
#define GBN 128
#define GBK 64
#define GSTR 72              // 64 halves + 8 pad
#define GA_ST (GBM * GSTR)   // 9216
#define GB_ST (GBN * GSTR)   // 9216
#define NKT   (Dd / GBK)     // 16
#define GEMM_SMEM ((3 * (GA_ST + GB_ST)) * 2)   // 110592 bytes

__global__ void __launch_bounds__(256, 2) gemm_xg_kernel(int useY0,
                                                         const float* __restrict__ bias) {
    const __half* A = useY0 ? g_y0f16 : g_xf16;
    extern __shared__ __align__(16) __half gsm[];
    __half* sA = gsm;                    // [3][GA_ST]
    __half* sB = sA + 3 * GA_ST;         // [3][GB_ST]

    const int tid = threadIdx.x, lane = tid & 31, warp = tid >> 5;
    const int m0 = blockIdx.y * GBM, n0 = blockIdx.x * GBN;
    const int wm = (warp & 1) * 64, wn = (warp >> 1) * 32;
    const int g = lane >> 2, q2 = (lane & 3) * 2;

    const int aRow = lane & 15,                       aCol = (lane >> 4) << 3;
    const int bRow = ((lane >> 4) << 3) + (lane & 7), bCol = ((lane >> 3) & 1) << 3;

    float acc[4][4][4];
#pragma unroll
    for (int a = 0; a < 4; a++)
#pragma unroll
        for (int b = 0; b < 4; b++)
#pragma unroll
            for (int c = 0; c < 4; c++) acc[a][b][c] = 0.f;

    auto fill = [&](int st, int kt) {
        const int k0 = kt * GBK;
#pragma unroll
        for (int i = 0; i < 4; i++) {
            int f = tid + i * 256, row = f >> 3, s = f & 7;
            cpa16(sA + st * GA_ST + row * GSTR + s * 8,
                  A + (size_t)(m0 + row) * Dd + k0 + s * 8);
        }
#pragma unroll
        for (int i = 0; i < 4; i++) {
            int f = tid + i * 256, row = f >> 3, s = f & 7;
            cpa16(sB + st * GB_ST + row * GSTR + s * 8,
                  g_whi + (size_t)(n0 + row) * Dd + k0 + s * 8);
        }
        CP_COMMIT();
    };

    fill(0, 0);
    fill(1, 1);

    for (int kt = 0; kt < NKT; ++kt) {
        if (kt + 2 < NKT) asm volatile("cp.async.wait_group 1;");
        else              asm volatile("cp.async.wait_group 0;");
        __syncthreads();
        if (kt + 2 < NKT) fill((kt + 2) % 3, kt + 2);
        const int st = kt % 3;
        const __half* pA = sA + st * GA_ST;
        const __half* pB = sB + st * GB_ST;
#pragma unroll
        for (int kk = 0; kk < GBK; kk += 16) {
            uint32_t af[4][4];
#pragma unroll
            for (int mt = 0; mt < 4; mt++)
                ldsm_x4(af[mt], pA + (wm + mt * 16 + aRow) * GSTR + kk + aCol);
#pragma unroll
            for (int p = 0; p < 2; p++) {
                uint32_t bf[4];
                ldsm_x4(bf, pB + (wn + p * 16 + bRow) * GSTR + kk + bCol);
#pragma unroll
                for (int mt = 0; mt < 4; mt++) {
                    mma_f16(acc[mt][2 * p],     af[mt], bf[0], bf[1]);
                    mma_f16(acc[mt][2 * p + 1], af[mt], bf[2], bf[3]);
                }
            }
        }
        __syncthreads();
    }
#pragma unroll
    for (int mt = 0; mt < 4; mt++) {
        int row = m0 + wm + mt * 16 + g;
#pragma unroll
        for (int nt = 0; nt < 4; nt++) {
            int col = n0 + wn + nt * 8 + q2;
            float b0 = __ldg(bias + col), b1 = __ldg(bias + col + 1);
            *(float2*)(g_xg + (size_t)row * G3 + col) =
                make_float2(acc[mt][nt][0] + b0, acc[mt][nt][1] + b1);
            *(float2*)(g_xg + (size_t)(row + 8) * G3 + col) =
                make_float2(acc[mt][nt][2] + b0, acc[mt][nt][3] + b1);
        }
    }
}

// ======== persistent recurrence: 2D partition, r/z W in registers, n W in smem ========
// R8 compute structure + per-warp producer-flag dependencies (no full barrier).
#define WSTR2 1032
#define RSMEM2 ((96 * WSTR2 + 8 * 16 * 128) * 2)   // 230,912 bytes

__global__ void __launch_bounds__(256, 1) recur_kernel(const float* __restrict__ h0,
                                                       const float* __restrict__ w_hh,
                                                       const float* __restrict__ b_hh,
                                                       float* __restrict__ yout) {
    const int layer0 = (yout == nullptr);
    extern __shared__ __align__(16) __half smem[];
    __half* sW = smem;                       // [96][WSTR2]
    __half* sH = sW + 96 * WSTR2;            // [8][16][128] swizzled

    const int tid = threadIdx.x, lane = tid & 31, warp = tid >> 5;
    const int w4 = warp & 3, wg = warp >> 2;
    const int cg = blockIdx.x & 31, bg = blockIdx.x >> 5;
    const int gid = blockIdx.x;
    const int g = lane >> 2, q2 = (lane & 3) * 2;

    const unsigned base = g_flags[gid * 32];   // all flags equal at entry (replay-safe)

    // ---- load W_hh into smem: rows = w4*24 + gate*8 + c8, cols = k
    for (int f = tid; f < 96 * 128; f += 256) {
        int rowp = f >> 7, seg = f & 127;
        int w4r = rowp / 24, rem = rowp - w4r * 24;
        int gate = rem >> 3, c8 = rem & 7;
        const float* src = w_hh + (size_t)(gate * Hh + cg * 32 + w4r * 8 + c8) * Hh + seg * 8;
        float4 v0 = *(const float4*)src;
        float4 v1 = *(const float4*)(src + 4);
        __half* d = sW + rowp * WSTR2 + seg * 8;
        ((__half2*)d)[0] = __floats2half2_rn(v0.x, v0.y);
        ((__half2*)d)[1] = __floats2half2_rn(v0.z, v0.w);
        ((__half2*)d)[2] = __floats2half2_rn(v1.x, v1.y);
        ((__half2*)d)[3] = __floats2half2_rn(v1.z, v1.w);
    }
    __syncthreads();

    // fragment selectors
    const int aRow = lane & 15, aSeg = lane >> 4;
    const int bRow = ((lane >> 4) << 3) + (lane & 7), bCol = ((lane >> 3) & 1) << 3;
    const int nRow = lane & 7;
    const int myChunk = wg * 4 + w4;
    const int kbase = wg * 512;
    const int wb = w4 * 24;

    // flag of the producer CTA for this lane's slice of my chunk (4 producers/chunk)
    const unsigned* flagp =
        &g_flags[((unsigned)(bg * 32 + ((myChunk << 2) | (lane & 3)))) * 32];

    // ---- r,z-gate W fragments -> registers (once, reused all 512 steps)
    uint32_t wreg[32][4];
#pragma unroll
    for (int kk = 0; kk < 32; kk++)
        ldsm_x4(wreg[kk], sW + (wb + bRow) * WSTR2 + kbase + kk * 16 + bCol);

    // per-thread output coords (wg0 does gate math for rows rb0 and rb0+8)
    const int ncol = cg * 32 + w4 * 8 + q2;
    const int rb0 = bg * 16 + g, rb1 = rb0 + 8;

    float bh[3][2];
#pragma unroll
    for (int gg = 0; gg < 3; gg++) {
        bh[gg][0] = b_hh[gg * Hh + ncol];
        bh[gg][1] = b_hh[gg * Hh + ncol + 1];
    }
    float hprev[4];
    hprev[0] = h0[rb0 * Hh + ncol];     hprev[1] = h0[rb0 * Hh + ncol + 1];
    hprev[2] = h0[rb1 * Hh + ncol];     hprev[3] = h0[rb1 * Hh + ncol + 1];

    const float* xgp0 = g_xg + (size_t)rb0 * T_ * G3 + ncol;
    const float* xgp1 = g_xg + (size_t)rb1 * T_ * G3 + ncol;

    for (int t = 0; t < T_; ++t) {
        const int pb = t & 1, nb = pb ^ 1;

        // per-warp dependency wait: only the 4 CTAs producing my chunk's columns
        if (t) {
            const unsigned tgt = base + (unsigned)t;
            unsigned v;
            do { asm volatile("ld.acquire.gpu.u32 %0, [%1];" : "=r"(v) : "l"(flagp)); }
            while (__any_sync(0xFFFFFFFFu, v < tgt));
        }

        // stream my chunk (16 rows x 128 halves, swizzled), one commit group
#pragma unroll
        for (int i = 0; i < 8; i++) {
            int f = lane + i * 32;
            int r = f >> 4, sj = f & 15;
            int sjs = sj ^ (r & 7);
            cpa16(sH + myChunk * 2048 + r * 128 + sjs * 8,
                  &g_hf16[pb][(size_t)(bg * 16 + r) * Hh + myChunk * KC + sj * 8]);
        }
        CP_COMMIT();

        // prefetch gate inputs (wg0 only) - overlaps with cp.async stream
        float xr[4], xz[4], xn[4];
        if (wg == 0) {
            float2 a0 = *(const float2*)(xgp0);
            float2 a1 = *(const float2*)(xgp0 + Hh);
            float2 a2 = *(const float2*)(xgp0 + 2 * Hh);
            float2 b0v = *(const float2*)(xgp1);
            float2 b1v = *(const float2*)(xgp1 + Hh);
            float2 b2v = *(const float2*)(xgp1 + 2 * Hh);
            xr[0] = a0.x; xr[1] = a0.y; xr[2] = b0v.x; xr[3] = b0v.y;
            xz[0] = a1.x; xz[1] = a1.y; xz[2] = b1v.x; xz[3] = b1v.y;
            xn[0] = a2.x; xn[1] = a2.y; xn[2] = b2v.x; xn[3] = b2v.y;
        }
        xgp0 += G3; xgp1 += G3;

        float acc[3][4];
#pragma unroll
        for (int gg = 0; gg < 3; gg++)
#pragma unroll
            for (int i = 0; i < 4; i++) acc[gg][i] = 0.f;

#pragma unroll
        for (int j = 0; j < 4; ++j) {
            if (w4 == j) asm volatile("cp.async.wait_group 0;");
            __syncthreads();
            const int slot = wg * 4 + j;
            const __half* hBase = sH + slot * 2048 + aRow * 128;
            const int sw = (aRow & 7);
#pragma unroll
            for (int kk = 0; kk < 8; kk++) {
                uint32_t af[4];
                int seg = kk * 2 + aSeg;
                ldsm_x4(af, hBase + (seg ^ sw) * 8);
                const int gcol = kbase + j * KC + kk * 16;
                uint32_t w2[2];
                ldsm_x2(w2, sW + (wb + 16 + nRow) * WSTR2 + gcol + bCol);
                const uint32_t* w01 = wreg[j * 8 + kk];
                mma_f16(acc[0], af, w01[0], w01[1]);
                mma_f16(acc[1], af, w01[2], w01[3]);
                mma_f16(acc[2], af, w2[0], w2[1]);
            }
        }

        // K-split reduction: wg1 -> smem scratch -> wg0 adds
        __syncthreads();
        float* scratch = (float*)sH;
        if (wg == 1) {
#pragma unroll
            for (int gg = 0; gg < 3; gg++)
#pragma unroll
                for (int i = 0; i < 4; i++)
                    scratch[(w4 * 32 + lane) * 12 + gg * 4 + i] = acc[gg][i];
        }
        __syncthreads();

        if (wg == 0) {
#pragma unroll
            for (int gg = 0; gg < 3; gg++)
#pragma unroll
                for (int i = 0; i < 4; i++)
                    acc[gg][i] += scratch[(w4 * 32 + lane) * 12 + gg * 4 + i];

            float hnew[4];
#pragma unroll
            for (int i = 0; i < 4; i++) {
                const int ci = i & 1;
                float r = 1.f / (1.f + __expf(-(xr[i] + acc[0][i] + bh[0][ci])));
                float z = 1.f / (1.f + __expf(-(xz[i] + acc[1][i] + bh[1][ci])));
                float n = tanhf(xn[i] + r * (acc[2][i] + bh[2][ci]));
                hnew[i] = (1.f - z) * n + z * hprev[i];
                hprev[i] = hnew[i];
            }

            if (layer0) {
                *(__half2*)&g_y0f16[((size_t)(rb0 * T_ + t)) * Hh + ncol] =
                    __floats2half2_rn(hnew[0], hnew[1]);
                *(__half2*)&g_y0f16[((size_t)(rb1 * T_ + t)) * Hh + ncol] =
                    __floats2half2_rn(hnew[2], hnew[3]);
                if (t == T_ - 1) {
                    *(float2*)&g_h0last[rb0 * Hh + ncol] = make_float2(hnew[0], hnew[1]);
                    *(float2*)&g_h0last[rb1 * Hh + ncol] = make_float2(hnew[2], hnew[3]);
                }
            } else {
                *(float2*)(yout + ((size_t)(rb0 * T_ + t)) * Hh + ncol) =
                    make_float2(hnew[0], hnew[1]);
                *(float2*)(yout + ((size_t)(rb1 * T_ + t)) * Hh + ncol) =
                    make_float2(hnew[2], hnew[3]);
            }
            *(__half2*)&g_hf16[nb][rb0 * Hh + ncol] = __floats2half2_rn(hnew[0], hnew[1]);
            *(__half2*)&g_hf16[nb][rb1 * Hh + ncol] = __floats2half2_rn(hnew[2], hnew[3]);

            // producer release: wg0 stored all of this CTA's h columns
            __threadfence();
            asm volatile("bar.sync 1, 128;" ::: "memory");
            if (tid == 0)
                asm volatile("st.release.gpu.u32 [%0], %1;"
                             :: "l"(&g_flags[gid * 32]), "r"(base + (unsigned)t + 1u));
        }
    }
}

// ---------------- tail: final hidden states ----------------
__global__ void tail_kernel(const float* __restrict__ y1, float* __restrict__ outh) {
    int i = blockIdx.x * blockDim.x + threadIdx.x;   // 0 .. 2*B*H-1
    if (i >= 2 * B_ * Hh) return;
    if (i < B_ * Hh) {
        outh[i] = g_h0last[i];
    } else {
        int j = i - B_ * Hh;
        int b = j >> 10, c = j & 1023;
        outh[i] = y1[((size_t)(b * T_ + (T_ - 1))) * Hh + c];
    }
}

// ---------------- launch ----------------
extern "C" void kernel_launch(void* const* d_in, const int* in_sizes, int n_in,
                              void* d_out, int out_size) {
    const float* x      = (const float*)d_in[0];
    const float* hidden = (const float*)d_in[1];
    const float* w_ih0  = (const float*)d_in[2];
    const float* w_hh0  = (const float*)d_in[3];
    const float* b_ih0  = (const float*)d_in[4];
    const float* b_hh0  = (const float*)d_in[5];
    const float* w_ih1  = (const float*)d_in[6];
    const float* w_hh1  = (const float*)d_in[7];
    const float* b_ih1  = (const float*)d_in[8];
    const float* b_hh1  = (const float*)d_in[9];
    float* out = (float*)d_out;

    cudaFuncSetAttribute(recur_kernel, cudaFuncAttributeMaxDynamicSharedMemorySize, RSMEM2);
    cudaFuncSetAttribute(gemm_xg_kernel, cudaFuncAttributeMaxDynamicSharedMemorySize, GEMM_SMEM);

    dim3 ggrid(G3 / GBN, MROWS / GBM);

    // layer 0
    convx_kernel<<<(MROWS * Dd / 4 + 255) / 256, 256>>>(x);
    convw_kernel<<<(G3 * Dd / 4 + 255) / 256, 256>>>(w_ih0);
    split_h_kernel<<<(B_ * Hh + 255) / 256, 256>>>(hidden);
    gemm_xg_kernel<<<ggrid, 256, GEMM_SMEM>>>(0, b_ih0);
    recur_kernel<<<NCTA, 256, RSMEM2>>>(hidden, w_hh0, b_hh0, nullptr);

    // layer 1
    convw_kernel<<<(G3 * Dd / 4 + 255) / 256, 256>>>(w_ih1);
    split_h_kernel<<<(B_ * Hh + 255) / 256, 256>>>(hidden + B_ * Hh);
    gemm_xg_kernel<<<ggrid, 256, GEMM_SMEM>>>(1, b_ih1);
    recur_kernel<<<NCTA, 256, RSMEM2>>>(hidden + B_ * Hh, w_hh1, b_hh1, out);

    // final hidden states (only if the output buffer includes them)
    if (out_size >= MROWS * Hh + 2 * B_ * Hh) {
        tail_kernel<<<(2 * B_ * Hh + 255) / 256, 256>>>(out, out + (size_t)MROWS * Hh);
    }
}

// round 12
// speedup vs baseline: 1.0530x; 1.0413x over previous
#include <cuda_runtime.h>
#include <cuda_fp16.h>
#include <cstdint>
#include <cstddef>

#define B_    64
#define T_    512
#define Dd    1024
#define Hh    1024
#define G3    3072
#define MROWS 32768          // B_*T_
#define NCTA  128            // persistent CTAs (<=148 SMs -> co-resident)
#define KC    128            // recurrence k-chunk

// ---------------- device scratch (no allocation) ----------------
__device__ float  g_xg[(size_t)MROWS * G3];      // input gates for current layer (fp32)
__device__ __half g_xf16[(size_t)MROWS * Dd];    // x as fp16
__device__ __half g_y0f16[(size_t)MROWS * Hh];   // layer-0 outputs fp16 (layer-1 GEMM input)
__device__ __half g_whi[(size_t)G3 * Dd];        // W_ih fp16 plane
__device__ __half g_hf16[2][B_ * Hh];            // h state fp16, double buffered
__device__ float  g_h0last[B_ * Hh];             // layer-0 final hidden (fp32)
__device__ unsigned g_flags[NCTA * 32];          // one flag per 128B line

// ---------------- helpers ----------------
__device__ __forceinline__ void mma_f16(float* c, const uint32_t* a, uint32_t b0, uint32_t b1) {
    asm volatile(
        "mma.sync.aligned.m16n8k16.row.col.f32.f16.f16.f32 "
        "{%0,%1,%2,%3}, {%4,%5,%6,%7}, {%8,%9}, {%0,%1,%2,%3};"
        : "+f"(c[0]), "+f"(c[1]), "+f"(c[2]), "+f"(c[3])
        : "r"(a[0]), "r"(a[1]), "r"(a[2]), "r"(a[3]), "r"(b0), "r"(b1));
}
__device__ __forceinline__ void ldsm_x4(uint32_t* r, const __half* p) {
    unsigned a = (unsigned)__cvta_generic_to_shared(p);
    asm volatile("ldmatrix.sync.aligned.m8n8.x4.shared.b16 {%0,%1,%2,%3}, [%4];"
                 : "=r"(r[0]), "=r"(r[1]), "=r"(r[2]), "=r"(r[3]) : "r"(a));
}
__device__ __forceinline__ void ldsm_x2(uint32_t* r, const __half* p) {
    unsigned a = (unsigned)__cvta_generic_to_shared(p);
    asm volatile("ldmatrix.sync.aligned.m8n8.x2.shared.b16 {%0,%1}, [%2];"
                 : "=r"(r[0]), "=r"(r[1]) : "r"(a));
}
__device__ __forceinline__ void cpa16(void* s, const void* g) {
    unsigned sa = (unsigned)__cvta_generic_to_shared(s);
    asm volatile("cp.async.cg.shared.global [%0], [%1], 16;" :: "r"(sa), "l"(g));
}
#define CP_COMMIT() asm volatile("cp.async.commit_group;")

// ---------------- conversion pre-pass kernels ----------------
__global__ void convx_kernel(const float* __restrict__ x) {
    size_t i = ((size_t)blockIdx.x * blockDim.x + threadIdx.x) * 4;
    if (i < (size_t)MROWS * Dd) {
        float4 v = *(const float4*)(x + i);
        *(__half2*)&g_xf16[i]     = __floats2half2_rn(v.x, v.y);
        *(__half2*)&g_xf16[i + 2] = __floats2half2_rn(v.z, v.w);
    }
}

__global__ void convw_kernel(const float* __restrict__ w) {
    size_t i = ((size_t)blockIdx.x * blockDim.x + threadIdx.x) * 4;
    if (i < (size_t)G3 * Dd) {
        float4 v = *(const float4*)(w + i);
        *(__half2*)&g_whi[i]     = __floats2half2_rn(v.x, v.y);
        *(__half2*)&g_whi[i + 2] = __floats2half2_rn(v.z, v.w);
    }
}

__global__ void split_h_kernel(const float* __restrict__ h0) {
    int i = blockIdx.x * blockDim.x + threadIdx.x;
    if (i < B_ * Hh) g_hf16[0][i] = __float2half_rn(h0[i]);
}

// ============ phase GEMM: g_xg[M,3072] = A_f16[M,1024] * Whi[3072,1024]^T + bias ============
// CTA tile 256x128, 8 warps of 64x64 (4M x 2N) -> 128 B/mma crossbar traffic
#define GBM 256
#define GBN 128
#define GBK 64
#define GSTR 72              // 64 halves + 8 pad
#define GA_ST (GBM * GSTR)   // 18432
#define GB_ST (GBN * GSTR)   // 9216
#define NKT   (Dd / GBK)     // 16
#define GEMM_SMEM ((3 * (GA_ST + GB_ST)) * 2)   // 165888 bytes

__global__ void __launch_bounds__(256, 1) gemm_xg_kernel(int useY0,
                                                         const float* __restrict__ bias) {
    const __half* A = useY0 ? g_y0f16 : g_xf16;
    extern __shared__ __align__(16) __half gsm[];
    __half* sA = gsm;                    // [3][GA_ST]
    __half* sB = sA + 3 * GA_ST;         // [3][GB_ST]

    const int tid = threadIdx.x, lane = tid & 31, warp = tid >> 5;
    const int m0 = blockIdx.y * GBM, n0 = blockIdx.x * GBN;
    const int wm = (warp >> 1) * 64, wn = (warp & 1) * 64;
    const int g = lane >> 2, q2 = (lane & 3) * 2;

    const int aRow = lane & 15,                       aCol = (lane >> 4) << 3;
    const int bRow = ((lane >> 4) << 3) + (lane & 7), bCol = ((lane >> 3) & 1) << 3;

    float acc[4][8][4];
#pragma unroll
    for (int a = 0; a < 4; a++)
#pragma unroll
        for (int b = 0; b < 8; b++)
#pragma unroll
            for (int c = 0; c < 4; c++) acc[a][b][c] = 0.f;

    auto fill = [&](int st, int kt) {
        const int k0 = kt * GBK;
#pragma unroll
        for (int i = 0; i < 8; i++) {                  // A: 256 rows x 8 segs
            int f = tid + i * 256, row = f >> 3, s = f & 7;
            cpa16(sA + st * GA_ST + row * GSTR + s * 8,
                  A + (size_t)(m0 + row) * Dd + k0 + s * 8);
        }
#pragma unroll
        for (int i = 0; i < 4; i++) {                  // B: 128 rows x 8 segs
            int f = tid + i * 256, row = f >> 3, s = f & 7;
            cpa16(sB + st * GB_ST + row * GSTR + s * 8,
                  g_whi + (size_t)(n0 + row) * Dd + k0 + s * 8);
        }
        CP_COMMIT();
    };

    fill(0, 0);
    fill(1, 1);

    for (int kt = 0; kt < NKT; ++kt) {
        if (kt + 2 < NKT) asm volatile("cp.async.wait_group 1;");
        else              asm volatile("cp.async.wait_group 0;");
        __syncthreads();
        if (kt + 2 < NKT) fill((kt + 2) % 3, kt + 2);
        const int st = kt % 3;
        const __half* pA = sA + st * GA_ST;
        const __half* pB = sB + st * GB_ST;
#pragma unroll
        for (int kk = 0; kk < GBK; kk += 16) {
            uint32_t af[4][4];
#pragma unroll
            for (int mt = 0; mt < 4; mt++)
                ldsm_x4(af[mt], pA + (wm + mt * 16 + aRow) * GSTR + kk + aCol);
#pragma unroll
            for (int p = 0; p < 4; p++) {
                uint32_t bf[4];
                ldsm_x4(bf, pB + (wn + p * 16 + bRow) * GSTR + kk + bCol);
#pragma unroll
                for (int mt = 0; mt < 4; mt++) {
                    mma_f16(acc[mt][2 * p],     af[mt], bf[0], bf[1]);
                    mma_f16(acc[mt][2 * p + 1], af[mt], bf[2], bf[3]);
                }
            }
        }
        __syncthreads();
    }
#pragma unroll
    for (int mt = 0; mt < 4; mt++) {
        int row = m0 + wm + mt * 16 + g;
#pragma unroll
        for (int nt = 0; nt < 8; nt++) {
            int col = n0 + wn + nt * 8 + q2;
            float b0 = __ldg(bias + col), b1 = __ldg(bias + col + 1);
            *(float2*)(g_xg + (size_t)row * G3 + col) =
                make_float2(acc[mt][nt][0] + b0, acc[mt][nt][1] + b1);
            *(float2*)(g_xg + (size_t)(row + 8) * G3 + col) =
                make_float2(acc[mt][nt][2] + b0, acc[mt][nt][3] + b1);
        }
    }
}

// ======== persistent recurrence: 2D partition, r/z W in registers, n W in smem ========
// (R8 kernel, byte-for-byte: full 32-CTA flag barrier, 4-round j-loop, wg1->wg0 tail)
#define WSTR2 1032
#define RSMEM2 ((96 * WSTR2 + 8 * 16 * 128) * 2)   // 230,912 bytes

__global__ void __launch_bounds__(256, 1) recur_kernel(const float* __restrict__ h0,
                                                       const float* __restrict__ w_hh,
                                                       const float* __restrict__ b_hh,
                                                       float* __restrict__ yout) {
    const int layer0 = (yout == nullptr);
    extern __shared__ __align__(16) __half smem[];
    __half* sW = smem;                       // [96][WSTR2]
    __half* sH = sW + 96 * WSTR2;            // [8][16][128] swizzled

    const int tid = threadIdx.x, lane = tid & 31, warp = tid >> 5;
    const int w4 = warp & 3, wg = warp >> 2;
    const int cg = blockIdx.x & 31, bg = blockIdx.x >> 5;
    const int gid = blockIdx.x;
    const int g = lane >> 2, q2 = (lane & 3) * 2;

    const unsigned base = g_flags[gid * 32];   // monotonic (replay-safe)

    // ---- load W_hh into smem: rows = w4*24 + gate*8 + c8, cols = k
    for (int f = tid; f < 96 * 128; f += 256) {
        int rowp = f >> 7, seg = f & 127;
        int w4r = rowp / 24, rem = rowp - w4r * 24;
        int gate = rem >> 3, c8 = rem & 7;
        const float* src = w_hh + (size_t)(gate * Hh + cg * 32 + w4r * 8 + c8) * Hh + seg * 8;
        float4 v0 = *(const float4*)src;
        float4 v1 = *(const float4*)(src + 4);
        __half* d = sW + rowp * WSTR2 + seg * 8;
        ((__half2*)d)[0] = __floats2half2_rn(v0.x, v0.y);
        ((__half2*)d)[1] = __floats2half2_rn(v0.z, v0.w);
        ((__half2*)d)[2] = __floats2half2_rn(v1.x, v1.y);
        ((__half2*)d)[3] = __floats2half2_rn(v1.z, v1.w);
    }
    __syncthreads();

    // fragment selectors
    const int aRow = lane & 15, aSeg = lane >> 4;
    const int bRow = ((lane >> 4) << 3) + (lane & 7), bCol = ((lane >> 3) & 1) << 3;
    const int nRow = lane & 7;
    const int myChunk = wg * 4 + w4;
    const int kbase = wg * 512;
    const int wb = w4 * 24;

    // ---- r,z-gate W fragments -> registers (once, reused all 512 steps)
    uint32_t wreg[32][4];
#pragma unroll
    for (int kk = 0; kk < 32; kk++)
        ldsm_x4(wreg[kk], sW + (wb + bRow) * WSTR2 + kbase + kk * 16 + bCol);

    // per-thread output coords (wg0 does gate math for rows rb0 and rb0+8)
    const int ncol = cg * 32 + w4 * 8 + q2;
    const int rb0 = bg * 16 + g, rb1 = rb0 + 8;

    float bh[3][2];
#pragma unroll
    for (int gg = 0; gg < 3; gg++) {
        bh[gg][0] = b_hh[gg * Hh + ncol];
        bh[gg][1] = b_hh[gg * Hh + ncol + 1];
    }
    float hprev[4];
    hprev[0] = h0[rb0 * Hh + ncol];     hprev[1] = h0[rb0 * Hh + ncol + 1];
    hprev[2] = h0[rb1 * Hh + ncol];     hprev[3] = h0[rb1 * Hh + ncol + 1];

    const float* xgp0 = g_xg + (size_t)rb0 * T_ * G3 + ncol;
    const float* xgp1 = g_xg + (size_t)rb1 * T_ * G3 + ncol;

    for (int t = 0; t < T_; ++t) {
        const int pb = t & 1, nb = pb ^ 1;

        if (t) {  // barrier among the 32 CTAs sharing this bg
            __threadfence();
            __syncthreads();
            if (tid == 0)
                asm volatile("st.release.gpu.u32 [%0], %1;"
                             :: "l"(&g_flags[gid * 32]), "r"(base + (unsigned)t));
            if (tid < 32) {
                unsigned v;
                do { asm volatile("ld.acquire.gpu.u32 %0, [%1];"
                                  : "=r"(v) : "l"(&g_flags[(bg * 32 + tid) * 32])); }
                while (v < base + (unsigned)t);
            }
            __syncthreads();
        }

        // each warp streams its chunk (16 rows x 128 halves, swizzled), one commit group
#pragma unroll
        for (int i = 0; i < 8; i++) {
            int f = lane + i * 32;
            int r = f >> 4, sj = f & 15;
            int sjs = sj ^ (r & 7);
            cpa16(sH + myChunk * 2048 + r * 128 + sjs * 8,
                  &g_hf16[pb][(size_t)(bg * 16 + r) * Hh + myChunk * KC + sj * 8]);
        }
        CP_COMMIT();

        // prefetch gate inputs (wg0 only) - overlaps with cp.async stream
        float xr[4], xz[4], xn[4];
        if (wg == 0) {
            float2 a0 = *(const float2*)(xgp0);
            float2 a1 = *(const float2*)(xgp0 + Hh);
            float2 a2 = *(const float2*)(xgp0 + 2 * Hh);
            float2 b0v = *(const float2*)(xgp1);
            float2 b1v = *(const float2*)(xgp1 + Hh);
            float2 b2v = *(const float2*)(xgp1 + 2 * Hh);
            xr[0] = a0.x; xr[1] = a0.y; xr[2] = b0v.x; xr[3] = b0v.y;
            xz[0] = a1.x; xz[1] = a1.y; xz[2] = b1v.x; xz[3] = b1v.y;
            xn[0] = a2.x; xn[1] = a2.y; xn[2] = b2v.x; xn[3] = b2v.y;
        }
        xgp0 += G3; xgp1 += G3;

        float acc[3][4];
#pragma unroll
        for (int gg = 0; gg < 3; gg++)
#pragma unroll
            for (int i = 0; i < 4; i++) acc[gg][i] = 0.f;

#pragma unroll
        for (int j = 0; j < 4; ++j) {
            if (w4 == j) asm volatile("cp.async.wait_group 0;");
            __syncthreads();
            const int slot = wg * 4 + j;
            const __half* hBase = sH + slot * 2048 + aRow * 128;
            const int sw = (aRow & 7);
#pragma unroll
            for (int kk = 0; kk < 8; kk++) {
                uint32_t af[4];
                int seg = kk * 2 + aSeg;
                ldsm_x4(af, hBase + (seg ^ sw) * 8);
                const int gcol = kbase + j * KC + kk * 16;
                uint32_t w2[2];
                ldsm_x2(w2, sW + (wb + 16 + nRow) * WSTR2 + gcol + bCol);
                const uint32_t* w01 = wreg[j * 8 + kk];
                mma_f16(acc[0], af, w01[0], w01[1]);
                mma_f16(acc[1], af, w01[2], w01[3]);
                mma_f16(acc[2], af, w2[0], w2[1]);
            }
        }

        // K-split reduction: wg1 -> smem scratch -> wg0 adds
        __syncthreads();
        float* scratch = (float*)sH;
        if (wg == 1) {
#pragma unroll
            for (int gg = 0; gg < 3; gg++)
#pragma unroll
                for (int i = 0; i < 4; i++)
                    scratch[(w4 * 32 + lane) * 12 + gg * 4 + i] = acc[gg][i];
        }
        __syncthreads();

        if (wg == 0) {
#pragma unroll
            for (int gg = 0; gg < 3; gg++)
#pragma unroll
                for (int i = 0; i < 4; i++)
                    acc[gg][i] += scratch[(w4 * 32 + lane) * 12 + gg * 4 + i];

            float hnew[4];
#pragma unroll
            for (int i = 0; i < 4; i++) {
                const int ci = i & 1;
                float r = 1.f / (1.f + __expf(-(xr[i] + acc[0][i] + bh[0][ci])));
                float z = 1.f / (1.f + __expf(-(xz[i] + acc[1][i] + bh[1][ci])));
                float n = tanhf(xn[i] + r * (acc[2][i] + bh[2][ci]));
                hnew[i] = (1.f - z) * n + z * hprev[i];
                hprev[i] = hnew[i];
            }

            if (layer0) {
                *(__half2*)&g_y0f16[((size_t)(rb0 * T_ + t)) * Hh + ncol] =
                    __floats2half2_rn(hnew[0], hnew[1]);
                *(__half2*)&g_y0f16[((size_t)(rb1 * T_ + t)) * Hh + ncol] =
                    __floats2half2_rn(hnew[2], hnew[3]);
                if (t == T_ - 1) {
                    *(float2*)&g_h0last[rb0 * Hh + ncol] = make_float2(hnew[0], hnew[1]);
                    *(float2*)&g_h0last[rb1 * Hh + ncol] = make_float2(hnew[2], hnew[3]);
                }
            } else {
                *(float2*)(yout + ((size_t)(rb0 * T_ + t)) * Hh + ncol) =
                    make_float2(hnew[0], hnew[1]);
                *(float2*)(yout + ((size_t)(rb1 * T_ + t)) * Hh + ncol) =
                    make_float2(hnew[2], hnew[3]);
            }
            *(__half2*)&g_hf16[nb][rb0 * Hh + ncol] = __floats2half2_rn(hnew[0], hnew[1]);
            *(__half2*)&g_hf16[nb][rb1 * Hh + ncol] = __floats2half2_rn(hnew[2], hnew[3]);
        }
    }
}

// ---------------- tail: final hidden states ----------------
__global__ void tail_kernel(const float* __restrict__ y1, float* __restrict__ outh) {
    int i = blockIdx.x * blockDim.x + threadIdx.x;   // 0 .. 2*B*H-1
    if (i >= 2 * B_ * Hh) return;
    if (i < B_ * Hh) {
        outh[i] = g_h0last[i];
    } else {
        int j = i - B_ * Hh;
        int b = j >> 10, c = j & 1023;
        outh[i] = y1[((size_t)(b * T_ + (T_ - 1))) * Hh + c];
    }
}

// ---------------- launch ----------------
extern "C" void kernel_launch(void* const* d_in, const int* in_sizes, int n_in,
                              void* d_out, int out_size) {
    const float* x      = (const float*)d_in[0];
    const float* hidden = (const float*)d_in[1];
    const float* w_ih0  = (const float*)d_in[2];
    const float* w_hh0  = (const float*)d_in[3];
    const float* b_ih0  = (const float*)d_in[4];
    const float* b_hh0  = (const float*)d_in[5];
    const float* w_ih1  = (const float*)d_in[6];
    const float* w_hh1  = (const float*)d_in[7];
    const float* b_ih1  = (const float*)d_in[8];
    const float* b_hh1  = (const float*)d_in[9];
    float* out = (float*)d_out;

    cudaFuncSetAttribute(recur_kernel, cudaFuncAttributeMaxDynamicSharedMemorySize, RSMEM2);
    cudaFuncSetAttribute(gemm_xg_kernel, cudaFuncAttributeMaxDynamicSharedMemorySize, GEMM_SMEM);

    dim3 ggrid(G3 / GBN, MROWS / GBM);

    // layer 0
    convx_kernel<<<(MROWS * Dd / 4 + 255) / 256, 256>>>(x);
    convw_kernel<<<(G3 * Dd / 4 + 255) / 256, 256>>>(w_ih0);
    split_h_kernel<<<(B_ * Hh + 255) / 256, 256>>>(hidden);
    gemm_xg_kernel<<<ggrid, 256, GEMM_SMEM>>>(0, b_ih0);
    recur_kernel<<<NCTA, 256, RSMEM2>>>(hidden, w_hh0, b_hh0, nullptr);

    // layer 1
    convw_kernel<<<(G3 * Dd / 4 + 255) / 256, 256>>>(w_ih1);
    split_h_kernel<<<(B_ * Hh + 255) / 256, 256>>>(hidden + B_ * Hh);
    gemm_xg_kernel<<<ggrid, 256, GEMM_SMEM>>>(1, b_ih1);
    recur_kernel<<<NCTA, 256, RSMEM2>>>(hidden + B_ * Hh, w_hh1, b_hh1, out);

    // final hidden states (only if the output buffer includes them)
    if (out_size >= MROWS * Hh + 2 * B_ * Hh) {
        tail_kernel<<<(2 * B_ * Hh + 255) / 256, 256>>>(out, out + (size_t)MROWS * Hh);
    }
}

// round 13
// speedup vs baseline: 1.0872x; 1.0325x over previous
#include <cuda_runtime.h>
#include <cuda_fp16.h>
#include <cstdint>
#include <cstddef>

#define B_    64
#define T_    512
#define Dd    1024
#define Hh    1024
#define G3    3072
#define MROWS 32768          // B_*T_
#define NCTA  128            // persistent CTAs (<=148 SMs -> co-resident)
#define KC    128            // recurrence k-chunk

// ---------------- device scratch (no allocation) ----------------
__device__ float  g_xg[(size_t)MROWS * G3];      // input gates for current layer (fp32)
__device__ __half g_xf16[(size_t)MROWS * Dd];    // x as fp16
__device__ __half g_y0f16[(size_t)MROWS * Hh];   // layer-0 outputs fp16 (layer-1 GEMM input)
__device__ __half g_whi[(size_t)G3 * Dd];        // W_ih fp16 plane
__device__ __half g_hf16[2][B_ * Hh];            // h state fp16, double buffered
__device__ float  g_h0last[B_ * Hh];             // layer-0 final hidden (fp32)
__device__ unsigned g_flags[NCTA * 32];          // one flag per 128B line

// ---------------- helpers ----------------
__device__ __forceinline__ void mma_f16(float* c, const uint32_t* a, uint32_t b0, uint32_t b1) {
    asm volatile(
        "mma.sync.aligned.m16n8k16.row.col.f32.f16.f16.f32 "
        "{%0,%1,%2,%3}, {%4,%5,%6,%7}, {%8,%9}, {%0,%1,%2,%3};"
        : "+f"(c[0]), "+f"(c[1]), "+f"(c[2]), "+f"(c[3])
        : "r"(a[0]), "r"(a[1]), "r"(a[2]), "r"(a[3]), "r"(b0), "r"(b1));
}
__device__ __forceinline__ void ldsm_x4(uint32_t* r, const __half* p) {
    unsigned a = (unsigned)__cvta_generic_to_shared(p);
    asm volatile("ldmatrix.sync.aligned.m8n8.x4.shared.b16 {%0,%1,%2,%3}, [%4];"
                 : "=r"(r[0]), "=r"(r[1]), "=r"(r[2]), "=r"(r[3]) : "r"(a));
}
__device__ __forceinline__ void ldsm_x2(uint32_t* r, const __half* p) {
    unsigned a = (unsigned)__cvta_generic_to_shared(p);
    asm volatile("ldmatrix.sync.aligned.m8n8.x2.shared.b16 {%0,%1}, [%2];"
                 : "=r"(r[0]), "=r"(r[1]) : "r"(a));
}
__device__ __forceinline__ void cpa16(void* s, const void* g) {
    unsigned sa = (unsigned)__cvta_generic_to_shared(s);
    asm volatile("cp.async.cg.shared.global [%0], [%1], 16;" :: "r"(sa), "l"(g));
}
#define CP_COMMIT() asm volatile("cp.async.commit_group;")

// ---------------- conversion pre-pass kernels ----------------
__global__ void convx_kernel(const float* __restrict__ x) {
    size_t i = ((size_t)blockIdx.x * blockDim.x + threadIdx.x) * 4;
    if (i < (size_t)MROWS * Dd) {
        float4 v = *(const float4*)(x + i);
        *(__half2*)&g_xf16[i]     = __floats2half2_rn(v.x, v.y);
        *(__half2*)&g_xf16[i + 2] = __floats2half2_rn(v.z, v.w);
    }
}

__global__ void convw_kernel(const float* __restrict__ w) {
    size_t i = ((size_t)blockIdx.x * blockDim.x + threadIdx.x) * 4;
    if (i < (size_t)G3 * Dd) {
        float4 v = *(const float4*)(w + i);
        *(__half2*)&g_whi[i]     = __floats2half2_rn(v.x, v.y);
        *(__half2*)&g_whi[i + 2] = __floats2half2_rn(v.z, v.w);
    }
}

__global__ void split_h_kernel(const float* __restrict__ h0) {
    int i = blockIdx.x * blockDim.x + threadIdx.x;
    if (i < B_ * Hh) g_hf16[0][i] = __float2half_rn(h0[i]);
}

// ============ phase GEMM: g_xg[M,3072] = A_f16[M,1024] * Whi[3072,1024]^T + bias ============
// CTA tile 128x128, 4 warps of 64x64 (2M x 2N), 128 threads, 2 CTAs/SM
#define GBM 128
#define GBN 128
#define GBK 64
#define GSTR 72              // 64 halves + 8 pad
#define GA_ST (GBM * GSTR)   // 9216
#define GB_ST (GBN * GSTR)   // 9216
#define NKT   (Dd / GBK)     // 16
#define GEMM_SMEM ((3 * (GA_ST + GB_ST)) * 2)   // 110592 bytes

__global__ void __launch_bounds__(128, 2) gemm_xg_kernel(int useY0,
                                                         const float* __restrict__ bias) {
    const __half* A = useY0 ? g_y0f16 : g_xf16;
    extern __shared__ __align__(16) __half gsm[];
    __half* sA = gsm;                    // [3][GA_ST]
    __half* sB = sA + 3 * GA_ST;         // [3][GB_ST]

    const int tid = threadIdx.x, lane = tid & 31, warp = tid >> 5;
    const int m0 = blockIdx.y * GBM, n0 = blockIdx.x * GBN;
    const int wm = (warp & 1) * 64, wn = (warp >> 1) * 64;
    const int g = lane >> 2, q2 = (lane & 3) * 2;

    const int aRow = lane & 15,                       aCol = (lane >> 4) << 3;
    const int bRow = ((lane >> 4) << 3) + (lane & 7), bCol = ((lane >> 3) & 1) << 3;

    float acc[4][8][4];
#pragma unroll
    for (int a = 0; a < 4; a++)
#pragma unroll
        for (int b = 0; b < 8; b++)
#pragma unroll
            for (int c = 0; c < 4; c++) acc[a][b][c] = 0.f;

    auto fill = [&](int st, int kt) {
        const int k0 = kt * GBK;
#pragma unroll
        for (int i = 0; i < 8; i++) {                  // A: 128 rows x 8 segs / 128 thr
            int f = tid + i * 128, row = f >> 3, s = f & 7;
            cpa16(sA + st * GA_ST + row * GSTR + s * 8,
                  A + (size_t)(m0 + row) * Dd + k0 + s * 8);
        }
#pragma unroll
        for (int i = 0; i < 8; i++) {                  // B: 128 rows x 8 segs / 128 thr
            int f = tid + i * 128, row = f >> 3, s = f & 7;
            cpa16(sB + st * GB_ST + row * GSTR + s * 8,
                  g_whi + (size_t)(n0 + row) * Dd + k0 + s * 8);
        }
        CP_COMMIT();
    };

    fill(0, 0);
    fill(1, 1);

    for (int kt = 0; kt < NKT; ++kt) {
        if (kt + 2 < NKT) asm volatile("cp.async.wait_group 1;");
        else              asm volatile("cp.async.wait_group 0;");
        __syncthreads();
        if (kt + 2 < NKT) fill((kt + 2) % 3, kt + 2);
        const int st = kt % 3;
        const __half* pA = sA + st * GA_ST;
        const __half* pB = sB + st * GB_ST;
#pragma unroll
        for (int kk = 0; kk < GBK; kk += 16) {
            uint32_t af[4][4];
#pragma unroll
            for (int mt = 0; mt < 4; mt++)
                ldsm_x4(af[mt], pA + (wm + mt * 16 + aRow) * GSTR + kk + aCol);
#pragma unroll
            for (int p = 0; p < 4; p++) {
                uint32_t bf[4];
                ldsm_x4(bf, pB + (wn + p * 16 + bRow) * GSTR + kk + bCol);
#pragma unroll
                for (int mt = 0; mt < 4; mt++) {
                    mma_f16(acc[mt][2 * p],     af[mt], bf[0], bf[1]);
                    mma_f16(acc[mt][2 * p + 1], af[mt], bf[2], bf[3]);
                }
            }
        }
        __syncthreads();
    }
#pragma unroll
    for (int mt = 0; mt < 4; mt++) {
        int row = m0 + wm + mt * 16 + g;
#pragma unroll
        for (int nt = 0; nt < 8; nt++) {
            int col = n0 + wn + nt * 8 + q2;
            float b0 = __ldg(bias + col), b1 = __ldg(bias + col + 1);
            *(float2*)(g_xg + (size_t)row * G3 + col) =
                make_float2(acc[mt][nt][0] + b0, acc[mt][nt][1] + b1);
            *(float2*)(g_xg + (size_t)(row + 8) * G3 + col) =
                make_float2(acc[mt][nt][2] + b0, acc[mt][nt][3] + b1);
        }
    }
}

// ======== persistent recurrence: 2D partition, r/z W in registers, n W in smem ========
// (R8 kernel, byte-for-byte: full 32-CTA flag barrier, 4-round j-loop, wg1->wg0 tail)
#define WSTR2 1032
#define RSMEM2 ((96 * WSTR2 + 8 * 16 * 128) * 2)   // 230,912 bytes

__global__ void __launch_bounds__(256, 1) recur_kernel(const float* __restrict__ h0,
                                                       const float* __restrict__ w_hh,
                                                       const float* __restrict__ b_hh,
                                                       float* __restrict__ yout) {
    const int layer0 = (yout == nullptr);
    extern __shared__ __align__(16) __half smem[];
    __half* sW = smem;                       // [96][WSTR2]
    __half* sH = sW + 96 * WSTR2;            // [8][16][128] swizzled

    const int tid = threadIdx.x, lane = tid & 31, warp = tid >> 5;
    const int w4 = warp & 3, wg = warp >> 2;
    const int cg = blockIdx.x & 31, bg = blockIdx.x >> 5;
    const int gid = blockIdx.x;
    const int g = lane >> 2, q2 = (lane & 3) * 2;

    const unsigned base = g_flags[gid * 32];   // monotonic (replay-safe)

    // ---- load W_hh into smem: rows = w4*24 + gate*8 + c8, cols = k
    for (int f = tid; f < 96 * 128; f += 256) {
        int rowp = f >> 7, seg = f & 127;
        int w4r = rowp / 24, rem = rowp - w4r * 24;
        int gate = rem >> 3, c8 = rem & 7;
        const float* src = w_hh + (size_t)(gate * Hh + cg * 32 + w4r * 8 + c8) * Hh + seg * 8;
        float4 v0 = *(const float4*)src;
        float4 v1 = *(const float4*)(src + 4);
        __half* d = sW + rowp * WSTR2 + seg * 8;
        ((__half2*)d)[0] = __floats2half2_rn(v0.x, v0.y);
        ((__half2*)d)[1] = __floats2half2_rn(v0.z, v0.w);
        ((__half2*)d)[2] = __floats2half2_rn(v1.x, v1.y);
        ((__half2*)d)[3] = __floats2half2_rn(v1.z, v1.w);
    }
    __syncthreads();

    // fragment selectors
    const int aRow = lane & 15, aSeg = lane >> 4;
    const int bRow = ((lane >> 4) << 3) + (lane & 7), bCol = ((lane >> 3) & 1) << 3;
    const int nRow = lane & 7;
    const int myChunk = wg * 4 + w4;
    const int kbase = wg * 512;
    const int wb = w4 * 24;

    // ---- r,z-gate W fragments -> registers (once, reused all 512 steps)
    uint32_t wreg[32][4];
#pragma unroll
    for (int kk = 0; kk < 32; kk++)
        ldsm_x4(wreg[kk], sW + (wb + bRow) * WSTR2 + kbase + kk * 16 + bCol);

    // per-thread output coords (wg0 does gate math for rows rb0 and rb0+8)
    const int ncol = cg * 32 + w4 * 8 + q2;
    const int rb0 = bg * 16 + g, rb1 = rb0 + 8;

    float bh[3][2];
#pragma unroll
    for (int gg = 0; gg < 3; gg++) {
        bh[gg][0] = b_hh[gg * Hh + ncol];
        bh[gg][1] = b_hh[gg * Hh + ncol + 1];
    }
    float hprev[4];
    hprev[0] = h0[rb0 * Hh + ncol];     hprev[1] = h0[rb0 * Hh + ncol + 1];
    hprev[2] = h0[rb1 * Hh + ncol];     hprev[3] = h0[rb1 * Hh + ncol + 1];

    const float* xgp0 = g_xg + (size_t)rb0 * T_ * G3 + ncol;
    const float* xgp1 = g_xg + (size_t)rb1 * T_ * G3 + ncol;

    for (int t = 0; t < T_; ++t) {
        const int pb = t & 1, nb = pb ^ 1;

        if (t) {  // barrier among the 32 CTAs sharing this bg
            __threadfence();
            __syncthreads();
            if (tid == 0)
                asm volatile("st.release.gpu.u32 [%0], %1;"
                             :: "l"(&g_flags[gid * 32]), "r"(base + (unsigned)t));
            if (tid < 32) {
                unsigned v;
                do { asm volatile("ld.acquire.gpu.u32 %0, [%1];"
                                  : "=r"(v) : "l"(&g_flags[(bg * 32 + tid) * 32])); }
                while (v < base + (unsigned)t);
            }
            __syncthreads();
        }

        // each warp streams its chunk (16 rows x 128 halves, swizzled), one commit group
#pragma unroll
        for (int i = 0; i < 8; i++) {
            int f = lane + i * 32;
            int r = f >> 4, sj = f & 15;
            int sjs = sj ^ (r & 7);
            cpa16(sH + myChunk * 2048 + r * 128 + sjs * 8,
                  &g_hf16[pb][(size_t)(bg * 16 + r) * Hh + myChunk * KC + sj * 8]);
        }
        CP_COMMIT();

        // prefetch gate inputs (wg0 only) - overlaps with cp.async stream
        float xr[4], xz[4], xn[4];
        if (wg == 0) {
            float2 a0 = *(const float2*)(xgp0);
            float2 a1 = *(const float2*)(xgp0 + Hh);
            float2 a2 = *(const float2*)(xgp0 + 2 * Hh);
            float2 b0v = *(const float2*)(xgp1);
            float2 b1v = *(const float2*)(xgp1 + Hh);
            float2 b2v = *(const float2*)(xgp1 + 2 * Hh);
            xr[0] = a0.x; xr[1] = a0.y; xr[2] = b0v.x; xr[3] = b0v.y;
            xz[0] = a1.x; xz[1] = a1.y; xz[2] = b1v.x; xz[3] = b1v.y;
            xn[0] = a2.x; xn[1] = a2.y; xn[2] = b2v.x; xn[3] = b2v.y;
        }
        xgp0 += G3; xgp1 += G3;

        float acc[3][4];
#pragma unroll
        for (int gg = 0; gg < 3; gg++)
#pragma unroll
            for (int i = 0; i < 4; i++) acc[gg][i] = 0.f;

#pragma unroll
        for (int j = 0; j < 4; ++j) {
            if (w4 == j) asm volatile("cp.async.wait_group 0;");
            __syncthreads();
            const int slot = wg * 4 + j;
            const __half* hBase = sH + slot * 2048 + aRow * 128;
            const int sw = (aRow & 7);
#pragma unroll
            for (int kk = 0; kk < 8; kk++) {
                uint32_t af[4];
                int seg = kk * 2 + aSeg;
                ldsm_x4(af, hBase + (seg ^ sw) * 8);
                const int gcol = kbase + j * KC + kk * 16;
                uint32_t w2[2];
                ldsm_x2(w2, sW + (wb + 16 + nRow) * WSTR2 + gcol + bCol);
                const uint32_t* w01 = wreg[j * 8 + kk];
                mma_f16(acc[0], af, w01[0], w01[1]);
                mma_f16(acc[1], af, w01[2], w01[3]);
                mma_f16(acc[2], af, w2[0], w2[1]);
            }
        }

        // K-split reduction: wg1 -> smem scratch -> wg0 adds
        __syncthreads();
        float* scratch = (float*)sH;
        if (wg == 1) {
#pragma unroll
            for (int gg = 0; gg < 3; gg++)
#pragma unroll
                for (int i = 0; i < 4; i++)
                    scratch[(w4 * 32 + lane) * 12 + gg * 4 + i] = acc[gg][i];
        }
        __syncthreads();

        if (wg == 0) {
#pragma unroll
            for (int gg = 0; gg < 3; gg++)
#pragma unroll
                for (int i = 0; i < 4; i++)
                    acc[gg][i] += scratch[(w4 * 32 + lane) * 12 + gg * 4 + i];

            float hnew[4];
#pragma unroll
            for (int i = 0; i < 4; i++) {
                const int ci = i & 1;
                float r = 1.f / (1.f + __expf(-(xr[i] + acc[0][i] + bh[0][ci])));
                float z = 1.f / (1.f + __expf(-(xz[i] + acc[1][i] + bh[1][ci])));
                float n = tanhf(xn[i] + r * (acc[2][i] + bh[2][ci]));
                hnew[i] = (1.f - z) * n + z * hprev[i];
                hprev[i] = hnew[i];
            }

            if (layer0) {
                *(__half2*)&g_y0f16[((size_t)(rb0 * T_ + t)) * Hh + ncol] =
                    __floats2half2_rn(hnew[0], hnew[1]);
                *(__half2*)&g_y0f16[((size_t)(rb1 * T_ + t)) * Hh + ncol] =
                    __floats2half2_rn(hnew[2], hnew[3]);
                if (t == T_ - 1) {
                    *(float2*)&g_h0last[rb0 * Hh + ncol] = make_float2(hnew[0], hnew[1]);
                    *(float2*)&g_h0last[rb1 * Hh + ncol] = make_float2(hnew[2], hnew[3]);
                }
            } else {
                *(float2*)(yout + ((size_t)(rb0 * T_ + t)) * Hh + ncol) =
                    make_float2(hnew[0], hnew[1]);
                *(float2*)(yout + ((size_t)(rb1 * T_ + t)) * Hh + ncol) =
                    make_float2(hnew[2], hnew[3]);
            }
            *(__half2*)&g_hf16[nb][rb0 * Hh + ncol] = __floats2half2_rn(hnew[0], hnew[1]);
            *(__half2*)&g_hf16[nb][rb1 * Hh + ncol] = __floats2half2_rn(hnew[2], hnew[3]);
        }
    }
}

// ---------------- tail: final hidden states ----------------
__global__ void tail_kernel(const float* __restrict__ y1, float* __restrict__ outh) {
    int i = blockIdx.x * blockDim.x + threadIdx.x;   // 0 .. 2*B*H-1
    if (i >= 2 * B_ * Hh) return;
    if (i < B_ * Hh) {
        outh[i] = g_h0last[i];
    } else {
        int j = i - B_ * Hh;
        int b = j >> 10, c = j & 1023;
        outh[i] = y1[((size_t)(b * T_ + (T_ - 1))) * Hh + c];
    }
}

// ---------------- launch ----------------
extern "C" void kernel_launch(void* const* d_in, const int* in_sizes, int n_in,
                              void* d_out, int out_size) {
    const float* x      = (const float*)d_in[0];
    const float* hidden = (const float*)d_in[1];
    const float* w_ih0  = (const float*)d_in[2];
    const float* w_hh0  = (const float*)d_in[3];
    const float* b_ih0  = (const float*)d_in[4];
    const float* b_hh0  = (const float*)d_in[5];
    const float* w_ih1  = (const float*)d_in[6];
    const float* w_hh1  = (const float*)d_in[7];
    const float* b_ih1  = (const float*)d_in[8];
    const float* b_hh1  = (const float*)d_in[9];
    float* out = (float*)d_out;

    cudaFuncSetAttribute(recur_kernel, cudaFuncAttributeMaxDynamicSharedMemorySize, RSMEM2);
    cudaFuncSetAttribute(gemm_xg_kernel, cudaFuncAttributeMaxDynamicSharedMemorySize, GEMM_SMEM);

    dim3 ggrid(G3 / GBN, MROWS / GBM);

    // layer 0
    convx_kernel<<<(MROWS * Dd / 4 + 255) / 256, 256>>>(x);
    convw_kernel<<<(G3 * Dd / 4 + 255) / 256, 256>>>(w_ih0);
    split_h_kernel<<<(B_ * Hh + 255) / 256, 256>>>(hidden);
    gemm_xg_kernel<<<ggrid, 128, GEMM_SMEM>>>(0, b_ih0);
    recur_kernel<<<NCTA, 256, RSMEM2>>>(hidden, w_hh0, b_hh0, nullptr);

    // layer 1
    convw_kernel<<<(G3 * Dd / 4 + 255) / 256, 256>>>(w_ih1);
    split_h_kernel<<<(B_ * Hh + 255) / 256, 256>>>(hidden + B_ * Hh);
    gemm_xg_kernel<<<ggrid, 128, GEMM_SMEM>>>(1, b_ih1);
    recur_kernel<<<NCTA, 256, RSMEM2>>>(hidden + B_ * Hh, w_hh1, b_hh1, out);

    // final hidden states (only if the output buffer includes them)
    if (out_size >= MROWS * Hh + 2 * B_ * Hh) {
        tail_kernel<<<(2 * B_ * Hh + 255) / 256, 256>>>(out, out + (size_t)MROWS * Hh);
    }
}

// round 14
// speedup vs baseline: 1.0959x; 1.0080x over previous
#include <cuda_runtime.h>
#include <cuda_fp16.h>
#include <cstdint>
#include <cstddef>

#define B_    64
#define T_    512
#define Dd    1024
#define Hh    1024
#define G3    3072
#define MROWS 32768          // B_*T_
#define NCTA  128            // persistent CTAs (<=148 SMs -> co-resident)
#define KC    128            // recurrence k-chunk

// ---------------- device scratch (no allocation) ----------------
__device__ float  g_xg[(size_t)MROWS * G3];      // input gates for current layer (fp32)
__device__ __half g_xf16[(size_t)MROWS * Dd];    // x as fp16
__device__ __half g_y0f16[(size_t)MROWS * Hh];   // layer-0 outputs fp16 (layer-1 GEMM input)
__device__ __half g_whi[(size_t)G3 * Dd];        // W_ih fp16 plane
__device__ __half g_hf16[2][B_ * Hh];            // h state fp16, double buffered
__device__ float  g_h0last[B_ * Hh];             // layer-0 final hidden (fp32)
__device__ unsigned g_flags[NCTA * 32];          // one flag per 128B line

// ---------------- helpers ----------------
__device__ __forceinline__ void mma_f16(float* c, const uint32_t* a, uint32_t b0, uint32_t b1) {
    asm volatile(
        "mma.sync.aligned.m16n8k16.row.col.f32.f16.f16.f32 "
        "{%0,%1,%2,%3}, {%4,%5,%6,%7}, {%8,%9}, {%0,%1,%2,%3};"
        : "+f"(c[0]), "+f"(c[1]), "+f"(c[2]), "+f"(c[3])
        : "r"(a[0]), "r"(a[1]), "r"(a[2]), "r"(a[3]), "r"(b0), "r"(b1));
}
__device__ __forceinline__ void ldsm_x4(uint32_t* r, const __half* p) {
    unsigned a = (unsigned)__cvta_generic_to_shared(p);
    asm volatile("ldmatrix.sync.aligned.m8n8.x4.shared.b16 {%0,%1,%2,%3}, [%4];"
                 : "=r"(r[0]), "=r"(r[1]), "=r"(r[2]), "=r"(r[3]) : "r"(a));
}
__device__ __forceinline__ void ldsm_x2(uint32_t* r, const __half* p) {
    unsigned a = (unsigned)__cvta_generic_to_shared(p);
    asm volatile("ldmatrix.sync.aligned.m8n8.x2.shared.b16 {%0,%1}, [%2];"
                 : "=r"(r[0]), "=r"(r[1]) : "r"(a));
}
__device__ __forceinline__ void cpa16(void* s, const void* g) {
    unsigned sa = (unsigned)__cvta_generic_to_shared(s);
    asm volatile("cp.async.cg.shared.global [%0], [%1], 16;" :: "r"(sa), "l"(g));
}
#define CP_COMMIT() asm volatile("cp.async.commit_group;")

// ---------------- conversion pre-pass kernels ----------------
__global__ void convx_kernel(const float* __restrict__ x) {
    size_t i = ((size_t)blockIdx.x * blockDim.x + threadIdx.x) * 4;
    if (i < (size_t)MROWS * Dd) {
        float4 v = *(const float4*)(x + i);
        *(__half2*)&g_xf16[i]     = __floats2half2_rn(v.x, v.y);
        *(__half2*)&g_xf16[i + 2] = __floats2half2_rn(v.z, v.w);
    }
}

__global__ void convw_kernel(const float* __restrict__ w) {
    size_t i = ((size_t)blockIdx.x * blockDim.x + threadIdx.x) * 4;
    if (i < (size_t)G3 * Dd) {
        float4 v = *(const float4*)(w + i);
        *(__half2*)&g_whi[i]     = __floats2half2_rn(v.x, v.y);
        *(__half2*)&g_whi[i + 2] = __floats2half2_rn(v.z, v.w);
    }
}

__global__ void split_h_kernel(const float* __restrict__ h0) {
    int i = blockIdx.x * blockDim.x + threadIdx.x;
    if (i < B_ * Hh) g_hf16[0][i] = __float2half_rn(h0[i]);
}

// ============ phase GEMM: g_xg[M,3072] = A_f16[M,1024] * Whi[3072,1024]^T + bias ============
// CTA tile 128x128, 4 warps of 64x64 (2M x 2N), 128 threads, 2 CTAs/SM
#define GBM 128
#define GBN 128
#define GBK 64
#define GSTR 72              // 64 halves + 8 pad
#define GA_ST (GBM * GSTR)   // 9216
#define GB_ST (GBN * GSTR)   // 9216
#define NKT   (Dd / GBK)     // 16
#define GEMM_SMEM ((3 * (GA_ST + GB_ST)) * 2)   // 110592 bytes

__global__ void __launch_bounds__(128, 2) gemm_xg_kernel(int useY0,
                                                         const float* __restrict__ bias) {
    const __half* A = useY0 ? g_y0f16 : g_xf16;
    extern __shared__ __align__(16) __half gsm[];
    __half* sA = gsm;                    // [3][GA_ST]
    __half* sB = sA + 3 * GA_ST;         // [3][GB_ST]

    const int tid = threadIdx.x, lane = tid & 31, warp = tid >> 5;
    const int m0 = blockIdx.y * GBM, n0 = blockIdx.x * GBN;
    const int wm = (warp & 1) * 64, wn = (warp >> 1) * 64;
    const int g = lane >> 2, q2 = (lane & 3) * 2;

    const int aRow = lane & 15,                       aCol = (lane >> 4) << 3;
    const int bRow = ((lane >> 4) << 3) + (lane & 7), bCol = ((lane >> 3) & 1) << 3;

    float acc[4][8][4];
#pragma unroll
    for (int a = 0; a < 4; a++)
#pragma unroll
        for (int b = 0; b < 8; b++)
#pragma unroll
            for (int c = 0; c < 4; c++) acc[a][b][c] = 0.f;

    auto fill = [&](int st, int kt) {
        const int k0 = kt * GBK;
#pragma unroll
        for (int i = 0; i < 8; i++) {                  // A: 128 rows x 8 segs / 128 thr
            int f = tid + i * 128, row = f >> 3, s = f & 7;
            cpa16(sA + st * GA_ST + row * GSTR + s * 8,
                  A + (size_t)(m0 + row) * Dd + k0 + s * 8);
        }
#pragma unroll
        for (int i = 0; i < 8; i++) {                  // B: 128 rows x 8 segs / 128 thr
            int f = tid + i * 128, row = f >> 3, s = f & 7;
            cpa16(sB + st * GB_ST + row * GSTR + s * 8,
                  g_whi + (size_t)(n0 + row) * Dd + k0 + s * 8);
        }
        CP_COMMIT();
    };

    fill(0, 0);
    fill(1, 1);

    for (int kt = 0; kt < NKT; ++kt) {
        if (kt + 2 < NKT) asm volatile("cp.async.wait_group 1;");
        else              asm volatile("cp.async.wait_group 0;");
        __syncthreads();
        if (kt + 2 < NKT) fill((kt + 2) % 3, kt + 2);
        const int st = kt % 3;
        const __half* pA = sA + st * GA_ST;
        const __half* pB = sB + st * GB_ST;
#pragma unroll
        for (int kk = 0; kk < GBK; kk += 16) {
            uint32_t af[4][4];
#pragma unroll
            for (int mt = 0; mt < 4; mt++)
                ldsm_x4(af[mt], pA + (wm + mt * 16 + aRow) * GSTR + kk + aCol);
#pragma unroll
            for (int p = 0; p < 4; p++) {
                uint32_t bf[4];
                ldsm_x4(bf, pB + (wn + p * 16 + bRow) * GSTR + kk + bCol);
#pragma unroll
                for (int mt = 0; mt < 4; mt++) {
                    mma_f16(acc[mt][2 * p],     af[mt], bf[0], bf[1]);
                    mma_f16(acc[mt][2 * p + 1], af[mt], bf[2], bf[3]);
                }
            }
        }
        __syncthreads();
    }
#pragma unroll
    for (int mt = 0; mt < 4; mt++) {
        int row = m0 + wm + mt * 16 + g;
#pragma unroll
        for (int nt = 0; nt < 8; nt++) {
            int col = n0 + wn + nt * 8 + q2;
            float b0 = __ldg(bias + col), b1 = __ldg(bias + col + 1);
            *(float2*)(g_xg + (size_t)row * G3 + col) =
                make_float2(acc[mt][nt][0] + b0, acc[mt][nt][1] + b1);
            *(float2*)(g_xg + (size_t)(row + 8) * G3 + col) =
                make_float2(acc[mt][nt][2] + b0, acc[mt][nt][3] + b1);
        }
    }
}

// ======== persistent recurrence: 2D partition, r/z W in registers, n W in smem ========
// (R8 kernel, byte-for-byte: full 32-CTA flag barrier, 4-round j-loop, wg1->wg0 tail)
#define WSTR2 1032
#define RSMEM2 ((96 * WSTR2 + 8 * 16 * 128) * 2)   // 230,912 bytes

__global__ void __launch_bounds__(256, 1) recur_kernel(const float* __restrict__ h0,
                                                       const float* __restrict__ w_hh,
                                                       const float* __restrict__ b_hh,
                                                       float* __restrict__ yout) {
    const int layer0 = (yout == nullptr);
    extern __shared__ __align__(16) __half smem[];
    __half* sW = smem;                       // [96][WSTR2]
    __half* sH = sW + 96 * WSTR2;            // [8][16][128] swizzled

    const int tid = threadIdx.x, lane = tid & 31, warp = tid >> 5;
    const int w4 = warp & 3, wg = warp >> 2;
    const int cg = blockIdx.x & 31, bg = blockIdx.x >> 5;
    const int gid = blockIdx.x;
    const int g = lane >> 2, q2 = (lane & 3) * 2;

    const unsigned base = g_flags[gid * 32];   // monotonic (replay-safe)

    // ---- load W_hh into smem: rows = w4*24 + gate*8 + c8, cols = k
    for (int f = tid; f < 96 * 128; f += 256) {
        int rowp = f >> 7, seg = f & 127;
        int w4r = rowp / 24, rem = rowp - w4r * 24;
        int gate = rem >> 3, c8 = rem & 7;
        const float* src = w_hh + (size_t)(gate * Hh + cg * 32 + w4r * 8 + c8) * Hh + seg * 8;
        float4 v0 = *(const float4*)src;
        float4 v1 = *(const float4*)(src + 4);
        __half* d = sW + rowp * WSTR2 + seg * 8;
        ((__half2*)d)[0] = __floats2half2_rn(v0.x, v0.y);
        ((__half2*)d)[1] = __floats2half2_rn(v0.z, v0.w);
        ((__half2*)d)[2] = __floats2half2_rn(v1.x, v1.y);
        ((__half2*)d)[3] = __floats2half2_rn(v1.z, v1.w);
    }
    __syncthreads();

    // fragment selectors
    const int aRow = lane & 15, aSeg = lane >> 4;
    const int bRow = ((lane >> 4) << 3) + (lane & 7), bCol = ((lane >> 3) & 1) << 3;
    const int nRow = lane & 7;
    const int myChunk = wg * 4 + w4;
    const int kbase = wg * 512;
    const int wb = w4 * 24;

    // ---- r,z-gate W fragments -> registers (once, reused all 512 steps)
    uint32_t wreg[32][4];
#pragma unroll
    for (int kk = 0; kk < 32; kk++)
        ldsm_x4(wreg[kk], sW + (wb + bRow) * WSTR2 + kbase + kk * 16 + bCol);

    // per-thread output coords (wg0 does gate math for rows rb0 and rb0+8)
    const int ncol = cg * 32 + w4 * 8 + q2;
    const int rb0 = bg * 16 + g, rb1 = rb0 + 8;

    float bh[3][2];
#pragma unroll
    for (int gg = 0; gg < 3; gg++) {
        bh[gg][0] = b_hh[gg * Hh + ncol];
        bh[gg][1] = b_hh[gg * Hh + ncol + 1];
    }
    float hprev[4];
    hprev[0] = h0[rb0 * Hh + ncol];     hprev[1] = h0[rb0 * Hh + ncol + 1];
    hprev[2] = h0[rb1 * Hh + ncol];     hprev[3] = h0[rb1 * Hh + ncol + 1];

    const float* xgp0 = g_xg + (size_t)rb0 * T_ * G3 + ncol;
    const float* xgp1 = g_xg + (size_t)rb1 * T_ * G3 + ncol;

    for (int t = 0; t < T_; ++t) {
        const int pb = t & 1, nb = pb ^ 1;

        if (t) {  // barrier among the 32 CTAs sharing this bg
            __threadfence();
            __syncthreads();
            if (tid == 0)
                asm volatile("st.release.gpu.u32 [%0], %1;"
                             :: "l"(&g_flags[gid * 32]), "r"(base + (unsigned)t));
            if (tid < 32) {
                unsigned v;
                do { asm volatile("ld.acquire.gpu.u32 %0, [%1];"
                                  : "=r"(v) : "l"(&g_flags[(bg * 32 + tid) * 32])); }
                while (v < base + (unsigned)t);
            }
            __syncthreads();
        }

        // each warp streams its chunk (16 rows x 128 halves, swizzled), one commit group
#pragma unroll
        for (int i = 0; i < 8; i++) {
            int f = lane + i * 32;
            int r = f >> 4, sj = f & 15;
            int sjs = sj ^ (r & 7);
            cpa16(sH + myChunk * 2048 + r * 128 + sjs * 8,
                  &g_hf16[pb][(size_t)(bg * 16 + r) * Hh + myChunk * KC + sj * 8]);
        }
        CP_COMMIT();

        // prefetch gate inputs (wg0 only) - overlaps with cp.async stream
        float xr[4], xz[4], xn[4];
        if (wg == 0) {
            float2 a0 = *(const float2*)(xgp0);
            float2 a1 = *(const float2*)(xgp0 + Hh);
            float2 a2 = *(const float2*)(xgp0 + 2 * Hh);
            float2 b0v = *(const float2*)(xgp1);
            float2 b1v = *(const float2*)(xgp1 + Hh);
            float2 b2v = *(const float2*)(xgp1 + 2 * Hh);
            xr[0] = a0.x; xr[1] = a0.y; xr[2] = b0v.x; xr[3] = b0v.y;
            xz[0] = a1.x; xz[1] = a1.y; xz[2] = b1v.x; xz[3] = b1v.y;
            xn[0] = a2.x; xn[1] = a2.y; xn[2] = b2v.x; xn[3] = b2v.y;
        }
        xgp0 += G3; xgp1 += G3;

        float acc[3][4];
#pragma unroll
        for (int gg = 0; gg < 3; gg++)
#pragma unroll
            for (int i = 0; i < 4; i++) acc[gg][i] = 0.f;

#pragma unroll
        for (int j = 0; j < 4; ++j) {
            if (w4 == j) asm volatile("cp.async.wait_group 0;");
            __syncthreads();
            const int slot = wg * 4 + j;
            const __half* hBase = sH + slot * 2048 + aRow * 128;
            const int sw = (aRow & 7);
#pragma unroll
            for (int kk = 0; kk < 8; kk++) {
                uint32_t af[4];
                int seg = kk * 2 + aSeg;
                ldsm_x4(af, hBase + (seg ^ sw) * 8);
                const int gcol = kbase + j * KC + kk * 16;
                uint32_t w2[2];
                ldsm_x2(w2, sW + (wb + 16 + nRow) * WSTR2 + gcol + bCol);
                const uint32_t* w01 = wreg[j * 8 + kk];
                mma_f16(acc[0], af, w01[0], w01[1]);
                mma_f16(acc[1], af, w01[2], w01[3]);
                mma_f16(acc[2], af, w2[0], w2[1]);
            }
        }

        // K-split reduction: wg1 -> smem scratch -> wg0 adds
        __syncthreads();
        float* scratch = (float*)sH;
        if (wg == 1) {
#pragma unroll
            for (int gg = 0; gg < 3; gg++)
#pragma unroll
                for (int i = 0; i < 4; i++)
                    scratch[(w4 * 32 + lane) * 12 + gg * 4 + i] = acc[gg][i];
        }
        __syncthreads();

        if (wg == 0) {
#pragma unroll
            for (int gg = 0; gg < 3; gg++)
#pragma unroll
                for (int i = 0; i < 4; i++)
                    acc[gg][i] += scratch[(w4 * 32 + lane) * 12 + gg * 4 + i];

            float hnew[4];
#pragma unroll
            for (int i = 0; i < 4; i++) {
                const int ci = i & 1;
                float r = 1.f / (1.f + __expf(-(xr[i] + acc[0][i] + bh[0][ci])));
                float z = 1.f / (1.f + __expf(-(xz[i] + acc[1][i] + bh[1][ci])));
                float n = tanhf(xn[i] + r * (acc[2][i] + bh[2][ci]));
                hnew[i] = (1.f - z) * n + z * hprev[i];
                hprev[i] = hnew[i];
            }

            if (layer0) {
                *(__half2*)&g_y0f16[((size_t)(rb0 * T_ + t)) * Hh + ncol] =
                    __floats2half2_rn(hnew[0], hnew[1]);
                *(__half2*)&g_y0f16[((size_t)(rb1 * T_ + t)) * Hh + ncol] =
                    __floats2half2_rn(hnew[2], hnew[3]);
                if (t == T_ - 1) {
                    *(float2*)&g_h0last[rb0 * Hh + ncol] = make_float2(hnew[0], hnew[1]);
                    *(float2*)&g_h0last[rb1 * Hh + ncol] = make_float2(hnew[2], hnew[3]);
                }
            } else {
                *(float2*)(yout + ((size_t)(rb0 * T_ + t)) * Hh + ncol) =
                    make_float2(hnew[0], hnew[1]);
                *(float2*)(yout + ((size_t)(rb1 * T_ + t)) * Hh + ncol) =
                    make_float2(hnew[2], hnew[3]);
            }
            *(__half2*)&g_hf16[nb][rb0 * Hh + ncol] = __floats2half2_rn(hnew[0], hnew[1]);
            *(__half2*)&g_hf16[nb][rb1 * Hh + ncol] = __floats2half2_rn(hnew[2], hnew[3]);
        }
    }
}

// ---------------- tail: final hidden states ----------------
__global__ void tail_kernel(const float* __restrict__ y1, float* __restrict__ outh) {
    int i = blockIdx.x * blockDim.x + threadIdx.x;   // 0 .. 2*B*H-1
    if (i >= 2 * B_ * Hh) return;
    if (i < B_ * Hh) {
        outh[i] = g_h0last[i];
    } else {
        int j = i - B_ * Hh;
        int b = j >> 10, c = j & 1023;
        outh[i] = y1[((size_t)(b * T_ + (T_ - 1))) * Hh + c];
    }
}

// ---------------- launch ----------------
extern "C" void kernel_launch(void* const* d_in, const int* in_sizes, int n_in,
                              void* d_out, int out_size) {
    const float* x      = (const float*)d_in[0];
    const float* hidden = (const float*)d_in[1];
    const float* w_ih0  = (const float*)d_in[2];
    const float* w_hh0  = (const float*)d_in[3];
    const float* b_ih0  = (const float*)d_in[4];
    const float* b_hh0  = (const float*)d_in[5];
    const float* w_ih1  = (const float*)d_in[6];
    const float* w_hh1  = (const float*)d_in[7];
    const float* b_ih1  = (const float*)d_in[8];
    const float* b_hh1  = (const float*)d_in[9];
    float* out = (float*)d_out;

    cudaFuncSetAttribute(recur_kernel, cudaFuncAttributeMaxDynamicSharedMemorySize, RSMEM2);
    cudaFuncSetAttribute(gemm_xg_kernel, cudaFuncAttributeMaxDynamicSharedMemorySize, GEMM_SMEM);

    dim3 ggrid(G3 / GBN, MROWS / GBM);

    // layer 0
    convx_kernel<<<(MROWS * Dd / 4 + 255) / 256, 256>>>(x);
    convw_kernel<<<(G3 * Dd / 4 + 255) / 256, 256>>>(w_ih0);
    split_h_kernel<<<(B_ * Hh + 255) / 256, 256>>>(hidden);
    gemm_xg_kernel<<<ggrid, 128, GEMM_SMEM>>>(0, b_ih0);
    recur_kernel<<<NCTA, 256, RSMEM2>>>(hidden, w_hh0, b_hh0, nullptr);

    // layer 1
    convw_kernel<<<(G3 * Dd / 4 + 255) / 256, 256>>>(w_ih1);
    split_h_kernel<<<(B_ * Hh + 255) / 256, 256>>>(hidden + B_ * Hh);
    gemm_xg_kernel<<<ggrid, 128, GEMM_SMEM>>>(1, b_ih1);
    recur_kernel<<<NCTA, 256, RSMEM2>>>(hidden + B_ * Hh, w_hh1, b_hh1, out);

    // final hidden states (only if the output buffer includes them)
    if (out_size >= MROWS * Hh + 2 * B_ * Hh) {
        tail_kernel<<<(2 * B_ * Hh + 255) / 256, 256>>>(out, out + (size_t)MROWS * Hh);
    }
}